// round 15
// baseline (speedup 1.0000x reference)
#include <cuda_runtime.h>
#include <cuda_fp16.h>
#include <cstdint>

// R12: fp16 2-MMA kernel (round 11) with TRUE occupancy 2 on the MLP kernels:
// smem request lowered to actual use (50KB/74.8KB) + __launch_bounds__(256,2).
// fp16 scheme's lower register pressure (~100 live) fits the 128-reg clamp.

#define NB 65536
#define DD 128
#define SLOT (NB*DD)
#define PSLOT (NB*64)

// ---------------- scratch ----------------
__device__ uint2 g_sPa[PSLOT];
__device__ uint2 g_sPv[PSLOT];
__device__ uint2 g_sPl[PSLOT];
__device__ uint2 g_sUni[PSLOT];
__device__ uint2 g_sBi[PSLOT];
__device__ uint2 g_sAV[PSLOT];
__device__ uint2 g_sAL[PSLOT];
__device__ uint2 g_sVL[PSLOT];
__device__ float g_G[3*SLOT];    // gav/gal/gvl fp32 (k2 -> k3)
__device__ float g_G2[6*SLOT];   // gf2 outputs fp32 (k4 -> k6)
__device__ float g_s[NB*16];

// packed 8B single-fp16 B-fragments: {b0, b1} per (k-step, n-tile, lane)
__device__ __align__(16) uint2 g_gfW1p[2][4096];
__device__ __align__(16) uint2 g_gfW2p[2][2048];
__device__ __align__(16) uint2 g_llW1p[6144];
__device__ __align__(16) uint2 g_llW2p[1024];
__device__ __align__(16) uint2 g_llW3p[2048];

extern __shared__ char smem_raw[];

// ---------------- helpers ----------------
__device__ __forceinline__ float wsum(float x){
  #pragma unroll
  for (int o=16;o;o>>=1) x += __shfl_xor_sync(0xffffffffu, x, o);
  return x;
}
__device__ __forceinline__ float wmax(float x){
  #pragma unroll
  for (int o=16;o;o>>=1) x = fmaxf(x, __shfl_xor_sync(0xffffffffu, x, o));
  return x;
}
__device__ __forceinline__ float dot4(float4 a, float4 b){
  return a.x*b.x + a.y*b.y + a.z*b.z + a.w*b.w;
}
__device__ __forceinline__ float max4(float4 a){ return fmaxf(fmaxf(a.x,a.y),fmaxf(a.z,a.w)); }
__device__ __forceinline__ float sum4(float4 a){ return a.x+a.y+a.z+a.w; }

__device__ __forceinline__ float fast_exp(float x){
  float e; asm("ex2.approx.f32 %0, %1;" : "=f"(e) : "f"(x*1.4426950408889634f));
  return e;
}
__device__ __forceinline__ float fast_tanh(float x){
  float e; asm("ex2.approx.f32 %0, %1;" : "=f"(e) : "f"(x*2.8853900817779268f));
  float r; asm("rcp.approx.f32 %0, %1;" : "=f"(r) : "f"(e+1.0f));
  return fmaf(-2.0f, r, 1.0f);
}

__device__ __forceinline__ uint32_t pack_h2(float x, float y){
  __half hx = __float2half_rn(x), hy = __float2half_rn(y);
  return (uint32_t)__half_as_ushort(hx) | ((uint32_t)__half_as_ushort(hy) << 16);
}
// fp16 split: hi = fp16(x), lo = fp16(x - hi)
__device__ __forceinline__ void split_pack2(float x, float y, uint32_t &h, uint32_t &l){
  __half hx = __float2half_rn(x), hy = __float2half_rn(y);
  float rx = x - __half2float(hx);
  float ry = y - __half2float(hy);
  h = (uint32_t)__half_as_ushort(hx) | ((uint32_t)__half_as_ushort(hy) << 16);
  l = pack_h2(rx, ry);
}
__device__ __forceinline__ uint2 split_u2(float x, float y){
  uint32_t h, l; split_pack2(x, y, h, l); return make_uint2(h, l);
}
__device__ __forceinline__ float2 unsplit(uint2 u){
  float2 a = __half22float2(*reinterpret_cast<__half2*>(&u.x));
  float2 b = __half22float2(*reinterpret_cast<__half2*>(&u.y));
  return make_float2(a.x + b.x, a.y + b.y);
}
__device__ __forceinline__ uint2 make_frag(float e0, float e1, float e2, float e3){
  return make_uint2(pack_h2(e0, e1), pack_h2(e2, e3));
}

#define MMA(c, a, bb0, bb1) \
  asm volatile("mma.sync.aligned.m16n8k16.row.col.f32.f16.f16.f32 " \
    "{%0,%1,%2,%3}, {%4,%5,%6,%7}, {%8,%9}, {%0,%1,%2,%3};" \
    : "+f"((c)[0]),"+f"((c)[1]),"+f"((c)[2]),"+f"((c)[3]) \
    : "r"((a)[0]),"r"((a)[1]),"r"((a)[2]),"r"((a)[3]), "r"(bb0),"r"(bb1))

__device__ __forceinline__ float lrelu(float x){ return (x > 0.f) ? x : 0.2f*x; }

// ---------------- K0: weight -> packed single-fp16 fragments ----------------
__global__ __launch_bounds__(256) void k0_conv(
    const float* __restrict__ gw1,  const float* __restrict__ gw2,
    const float* __restrict__ g2w1, const float* __restrict__ g2w2,
    const float* __restrict__ lw1,  const float* __restrict__ lw2,
    const float* __restrict__ lw3)
{
  int y = blockIdx.y;
  int e = blockIdx.x*256 + threadIdx.x;
  if (y < 2){
    if (e < 4096){
      int kk = e>>8, rem = e&255, nt = rem>>5, lane = rem&31, g = lane>>2, tg = lane&3;
      int n = nt*8+g, k = kk*16+tg*2;
      const float* w1 = y ? g2w1 : gw1;   // [256,64]
      g_gfW1p[y][e] = make_frag(w1[k*64+n], w1[(k+1)*64+n], w1[(k+8)*64+n], w1[(k+9)*64+n]);
    } else if (e < 6144){
      int f = e-4096;
      int q = f>>8, rem = f&255, nt = rem>>5, lane = rem&31, g = lane>>2, tg = lane&3;
      int nh = q>>2, kt = q&3;
      int n = (nh*8+nt)*8+g, k = kt*16+tg*2;
      const float* w2 = y ? g2w2 : gw2;   // [64,128]
      g_gfW2p[y][f] = make_frag(w2[k*128+n], w2[(k+1)*128+n], w2[(k+8)*128+n], w2[(k+9)*128+n]);
    }
  } else {
    if (e < 6144){
      int kk = e>>8, rem = e&255, nt = rem>>5, lane = rem&31, g = lane>>2, tg = lane&3;
      int n = nt*8+g, k = kk*16+tg*2;     // lw1 [384,64]
      g_llW1p[e] = make_frag(lw1[k*64+n], lw1[(k+1)*64+n], lw1[(k+8)*64+n], lw1[(k+9)*64+n]);
    } else if (e < 7168){
      int f = e-6144;
      int kt = f>>8, rem = f&255, nt = rem>>5, lane = rem&31, g = lane>>2, tg = lane&3;
      int n = nt*8+g, k = kt*16+tg*2;     // lw2 [64,64]
      g_llW2p[f] = make_frag(lw2[k*64+n], lw2[(k+1)*64+n], lw2[(k+8)*64+n], lw2[(k+9)*64+n]);
    } else if (e < 9216){
      int f = e-7168;
      int q = f>>8, rem = f&255, nt = rem>>5, lane = rem&31, g = lane>>2, tg = lane&3;
      int nh = q>>2, kt = q&3;
      int n = (nh*8+nt)*8+g, k = kt*16+tg*2;  // lw3 [64,128]
      g_llW3p[f] = make_frag(lw3[k*128+n], lw3[(k+1)*128+n], lw3[(k+8)*128+n], lw3[(k+9)*128+n]);
    }
  }
}

// ---------------- K1: rowwise pre ----------------
__global__ __launch_bounds__(256) void k1_pre(
    const float* __restrict__ L, const float* __restrict__ A,
    const float* __restrict__ V, const float* __restrict__ attw,
    const float* __restrict__ attb)
{
  int gw   = (int)((blockIdx.x*blockDim.x + threadIdx.x) >> 5);
  int lane = threadIdx.x & 31;
  size_t base = (size_t)gw*DD + lane*4;
  size_t pbase = (size_t)gw*64 + lane*2;

  float4 av = *(const float4*)(A+base);
  float4 vv = *(const float4*)(V+base);
  float4 lv = *(const float4*)(L+base);
  float4 wv = *(const float4*)(attw + lane*4);
  float bb = attb[0];

  float sa = fast_tanh(wsum(dot4(av,wv)) + bb);
  float sv = fast_tanh(wsum(dot4(vv,wv)) + bb);
  float sl = fast_tanh(wsum(dot4(lv,wv)) + bb);

  float4 u;
  u.x = (sa*av.x + sv*vv.x + sl*lv.x)*(1.0f/3.0f);
  u.y = (sa*av.y + sv*vv.y + sl*lv.y)*(1.0f/3.0f);
  u.z = (sa*av.z + sv*vv.z + sl*lv.z)*(1.0f/3.0f);
  u.w = (sa*av.w + sv*vv.w + sl*lv.w)*(1.0f/3.0f);
  g_sUni[pbase]   = split_u2(u.x, u.y);
  g_sUni[pbase+1] = split_u2(u.z, u.w);

  float m = wmax(max4(av));
  float4 pa = make_float4(fast_exp(av.x-m),fast_exp(av.y-m),fast_exp(av.z-m),fast_exp(av.w-m));
  float inv = 1.0f/wsum(sum4(pa));
  pa.x*=inv; pa.y*=inv; pa.z*=inv; pa.w*=inv;
  m = wmax(max4(vv));
  float4 pv = make_float4(fast_exp(vv.x-m),fast_exp(vv.y-m),fast_exp(vv.z-m),fast_exp(vv.w-m));
  inv = 1.0f/wsum(sum4(pv));
  pv.x*=inv; pv.y*=inv; pv.z*=inv; pv.w*=inv;
  m = wmax(max4(lv));
  float4 pl = make_float4(fast_exp(lv.x-m),fast_exp(lv.y-m),fast_exp(lv.z-m),fast_exp(lv.w-m));
  inv = 1.0f/wsum(sum4(pl));
  pl.x*=inv; pl.y*=inv; pl.z*=inv; pl.w*=inv;

  g_sPa[pbase]   = split_u2(pa.x, pa.y);
  g_sPa[pbase+1] = split_u2(pa.z, pa.w);
  g_sPv[pbase]   = split_u2(pv.x, pv.y);
  g_sPv[pbase+1] = split_u2(pv.z, pv.w);
  g_sPl[pbase]   = split_u2(pl.x, pl.y);
  g_sPl[pbase+1] = split_u2(pl.z, pl.w);

  float dav = wsum(dot4(pa,pv));
  float dal = wsum(dot4(pa,pl));
  float dvl = wsum(dot4(pv,pl));

  float sav = (sa+sv)/(dav+0.5f);
  float sal = (sa+sl)/(dal+0.5f);
  float svl = (sl+sv)/(dvl+0.5f);

  float m3 = fmaxf(sav,fmaxf(sal,svl));
  float e0 = fast_exp(sav-m3), e1 = fast_exp(sal-m3), e2 = fast_exp(svl-m3);
  float r3 = 1.0f/(e0+e1+e2);

  if (lane==0){
    float* s = g_s + (size_t)gw*16;
    s[0]=sa; s[1]=sv; s[2]=sl;
    s[3]=sav; s[4]=sal; s[5]=svl;
    s[6]=e0*r3; s[7]=e1*r3; s[8]=e2*r3;
  }
}

// ---------------- 2-layer MLP body (packed fp16 weights in smem, occ 2) ----------------
// smem: 0 b1s(256B) | 256 b2s(512B) | 1024 W1p(32768) | 33792 W2p(16384) = 50176
#define SMEM_MLP_REQ 50176

__device__ __forceinline__ void mlp2_body(
    const uint2* __restrict__ x1, const uint2* __restrict__ x2,
    float* __restrict__ outp, int row0, int n2slot)
{
  const float* b1s = (const float*)(smem_raw);
  const float* b2s = (const float*)(smem_raw + 256);
  const uint2* W1p = (const uint2*)(smem_raw + 1024);
  const uint2* W2p = (const uint2*)(smem_raw + 33792);

  int tid = threadIdx.x;
  int w = tid >> 5, lane = tid & 31;
  int g = lane >> 2, tg = lane & 3;
  int r0 = row0 + w*16 + g;
  int r1 = r0 + 8;

  // -------- stage 1: concat(x1,x2)[128x256] @ W1 --------
  float acc[8][4];
  #pragma unroll
  for (int i=0;i<8;i++){ acc[i][0]=0.f; acc[i][1]=0.f; acc[i][2]=0.f; acc[i][3]=0.f; }

  uint2 cu0, cu1, cu2, cu3;
  {
    const uint2* p0 = x1 + (size_t)r0*64 + tg;
    const uint2* p1 = x1 + (size_t)r1*64 + tg;
    cu0 = p0[0]; cu1 = p1[0]; cu2 = p0[4]; cu3 = p1[4];
  }
  #pragma unroll 1
  for (int kk = 0; kk < 16; kk++){
    uint32_t ah[4], al[4];
    ah[0]=cu0.x; al[0]=cu0.y;
    ah[1]=cu1.x; al[1]=cu1.y;
    ah[2]=cu2.x; al[2]=cu2.y;
    ah[3]=cu3.x; al[3]=cu3.y;
    if (kk < 15){
      int k2i = kk + 1;
      const uint2* s2 = (k2i < 8) ? x1 : x2;
      int pi2 = (k2i & 7)*8 + tg;
      const uint2* p0 = s2 + (size_t)r0*64 + pi2;
      const uint2* p1 = s2 + (size_t)r1*64 + pi2;
      cu0 = p0[0]; cu1 = p1[0]; cu2 = p0[4]; cu3 = p1[4];
    }
    const uint2* bp = W1p + kk*256 + lane;
    #pragma unroll
    for (int nt = 0; nt < 8; nt++){
      uint2 B = bp[nt*32];
      MMA(acc[nt], ah, B.x, B.y);
      MMA(acc[nt], al, B.x, B.y);
    }
  }

  // -------- H = lrelu(acc + b1) -> frags --------
  uint32_t hh[4][4], hl[4][4];
  #pragma unroll
  for (int kt = 0; kt < 4; kt++){
    float* t0 = acc[2*kt];
    float* t1 = acc[2*kt+1];
    int c0 = kt*16 + tg*2;
    float bA = b1s[c0], bB = b1s[c0+1], bC = b1s[c0+8], bD = b1s[c0+9];
    split_pack2(lrelu(t0[0]+bA), lrelu(t0[1]+bB), hh[kt][0], hl[kt][0]);
    split_pack2(lrelu(t0[2]+bA), lrelu(t0[3]+bB), hh[kt][1], hl[kt][1]);
    split_pack2(lrelu(t1[0]+bC), lrelu(t1[1]+bD), hh[kt][2], hl[kt][2]);
    split_pack2(lrelu(t1[2]+bC), lrelu(t1[3]+bD), hh[kt][3], hl[kt][3]);
  }

  // -------- stage 2: H[128x64] @ W2[64x128] --------
  float scv0 = 0.f, scv1 = 0.f;
  if (n2slot >= 0){
    scv0 = g_s[(size_t)r0*16 + n2slot];
    scv1 = g_s[(size_t)r1*16 + n2slot];
  }
  #pragma unroll 1
  for (int nh = 0; nh < 2; nh++){
    float acc2[8][4];
    #pragma unroll
    for (int i=0;i<8;i++){ acc2[i][0]=0.f; acc2[i][1]=0.f; acc2[i][2]=0.f; acc2[i][3]=0.f; }
    const uint2* bp2 = W2p + nh*1024 + lane;
    #pragma unroll
    for (int nt = 0; nt < 8; nt++){
      #pragma unroll
      for (int kt = 0; kt < 4; kt++){
        uint2 B = bp2[kt*256 + nt*32];
        MMA(acc2[nt], hh[kt], B.x, B.y);
        MMA(acc2[nt], hl[kt], B.x, B.y);
      }
    }
    #pragma unroll
    for (int nt = 0; nt < 8; nt++){
      int col = (nh*8+nt)*8 + tg*2;
      float v0 = fast_tanh(acc2[nt][0] + b2s[col]);
      float v1 = fast_tanh(acc2[nt][1] + b2s[col+1]);
      float v2 = fast_tanh(acc2[nt][2] + b2s[col]);
      float v3 = fast_tanh(acc2[nt][3] + b2s[col+1]);
      if (n2slot >= 0){
        v0 = fast_tanh(scv0*v0); v1 = fast_tanh(scv0*v1);
        v2 = fast_tanh(scv1*v2); v3 = fast_tanh(scv1*v3);
      }
      *(float2*)(outp + (size_t)r0*DD + col) = make_float2(v0, v1);
      *(float2*)(outp + (size_t)r1*DD + col) = make_float2(v2, v3);
    }
  }
}

__device__ __forceinline__ void stage_mlp_weights(int set,
    const float* __restrict__ b1, const float* __restrict__ b2)
{
  float* b1s = (float*)(smem_raw);
  float* b2s = (float*)(smem_raw + 256);
  uint4* dW1 = (uint4*)(smem_raw + 1024);
  uint4* dW2 = (uint4*)(smem_raw + 33792);
  int tid = threadIdx.x;
  const uint4* s1 = (const uint4*)g_gfW1p[set];
  const uint4* s2 = (const uint4*)g_gfW2p[set];
  #pragma unroll
  for (int i = tid; i < 2048; i += 256) dW1[i] = s1[i];
  #pragma unroll
  for (int i = tid; i < 1024; i += 256) dW2[i] = s2[i];
  if (tid < 64)  b1s[tid] = b1[tid];
  if (tid < 128) b2s[tid] = b2[tid];
  __syncthreads();
}

// ---------------- K2 / K4 (occ 2) ----------------
__global__ __launch_bounds__(256,2) void k2_tc(const float* __restrict__ b1, const float* __restrict__ b2)
{
  stage_mlp_weights(0, b1, b2);
  const uint2 *x1, *x2;
  int p = blockIdx.y;
  if (p==0){ x1=g_sPa; x2=g_sPv; }
  else if (p==1){ x1=g_sPa; x2=g_sPl; }
  else { x1=g_sPv; x2=g_sPl; }
  mlp2_body(x1, x2, g_G + (size_t)p*SLOT, blockIdx.x*128, -1);
}

__global__ __launch_bounds__(256,2) void k4_tc(const float* __restrict__ b1, const float* __restrict__ b2)
{
  stage_mlp_weights(1, b1, b2);
  const uint2 *x1, *x2;
  int p = blockIdx.y;
  switch(p){
    case 0: x1=g_sAV; x2=g_sVL; break;
    case 1: x1=g_sAV; x2=g_sAL; break;
    case 2: x1=g_sVL; x2=g_sAL; break;
    case 3: x1=g_sAV; x2=g_sPl; break;
    case 4: x1=g_sAL; x2=g_sPv; break;
    default:x1=g_sVL; x2=g_sPa; break;
  }
  mlp2_body(x1, x2, g_G2 + (size_t)p*SLOT, blockIdx.x*128, 9+p);
}

// ---------------- K3: rowwise mid ----------------
__global__ __launch_bounds__(256) void k3_mid()
{
  int gw   = (int)((blockIdx.x*blockDim.x + threadIdx.x) >> 5);
  int lane = threadIdx.x & 31;
  size_t base = (size_t)gw*DD + lane*4;
  size_t pbase = (size_t)gw*64 + lane*2;

  float4 gav = *(const float4*)(g_G + base);
  float4 gal = *(const float4*)(g_G + (size_t)SLOT + base);
  float4 gvl = *(const float4*)(g_G + 2*(size_t)SLOT + base);

  float2 t0, t1;
  t0 = unsplit(g_sPa[pbase]); t1 = unsplit(g_sPa[pbase+1]);
  float4 pa = make_float4(t0.x, t0.y, t1.x, t1.y);
  t0 = unsplit(g_sPv[pbase]); t1 = unsplit(g_sPv[pbase+1]);
  float4 pv = make_float4(t0.x, t0.y, t1.x, t1.y);
  t0 = unsplit(g_sPl[pbase]); t1 = unsplit(g_sPl[pbase+1]);
  float4 pl = make_float4(t0.x, t0.y, t1.x, t1.y);

  float m, inv;
  m = wmax(max4(gav));
  float4 A2 = make_float4(fast_exp(gav.x-m),fast_exp(gav.y-m),fast_exp(gav.z-m),fast_exp(gav.w-m));
  inv = 1.0f/wsum(sum4(A2)); A2.x*=inv; A2.y*=inv; A2.z*=inv; A2.w*=inv;
  m = wmax(max4(gal));
  float4 L2 = make_float4(fast_exp(gal.x-m),fast_exp(gal.y-m),fast_exp(gal.z-m),fast_exp(gal.w-m));
  inv = 1.0f/wsum(sum4(L2)); L2.x*=inv; L2.y*=inv; L2.z*=inv; L2.w*=inv;
  m = wmax(max4(gvl));
  float4 V2 = make_float4(fast_exp(gvl.x-m),fast_exp(gvl.y-m),fast_exp(gvl.z-m),fast_exp(gvl.w-m));
  inv = 1.0f/wsum(sum4(V2)); V2.x*=inv; V2.y*=inv; V2.z*=inv; V2.w*=inv;

  float d0 = wsum(dot4(A2,V2));
  float d1 = wsum(dot4(A2,L2));
  float d2 = wsum(dot4(L2,V2));
  float d3 = wsum(dot4(A2,pl));
  float d4 = wsum(dot4(L2,pv));
  float d5 = wsum(dot4(V2,pa));

  const float* s = g_s + (size_t)gw*16;
  float sa1=s[0], sv1=s[1], sl1=s[2], sav=s[3], sal=s[4], svl=s[5];
  float nm0=s[6], nm1=s[7], nm2=s[8];

  float e0=(sav+svl)/(d0+0.5f);
  float e1=(sav+sal)/(d1+0.5f);
  float e2=(sal+svl)/(d2+0.5f);
  float e3=(sav+sl1)/(d3+0.5f);
  float e4=(sal+sv1)/(d4+0.5f);
  float e5=(sa1+svl)/(d5+0.5f);
  float mm = fmaxf(fmaxf(fmaxf(e0,e1),fmaxf(e2,e3)),fmaxf(e4,e5));
  float x0=fast_exp(e0-mm),x1=fast_exp(e1-mm),x2=fast_exp(e2-mm);
  float x3=fast_exp(e3-mm),x4=fast_exp(e4-mm),x5=fast_exp(e5-mm);
  float ri = 1.0f/(x0+x1+x2+x3+x4+x5);
  if (lane==0){
    float* sw = g_s + (size_t)gw*16;
    sw[9]=x0*ri; sw[10]=x1*ri; sw[11]=x2*ri; sw[12]=x3*ri; sw[13]=x4*ri; sw[14]=x5*ri;
  }

  float4 AV = make_float4(fast_tanh(nm0*gav.x),fast_tanh(nm0*gav.y),fast_tanh(nm0*gav.z),fast_tanh(nm0*gav.w));
  float4 AL = make_float4(fast_tanh(nm1*gal.x),fast_tanh(nm1*gal.y),fast_tanh(nm1*gal.z),fast_tanh(nm1*gal.w));
  float4 VL = make_float4(fast_tanh(nm2*gvl.x),fast_tanh(nm2*gvl.y),fast_tanh(nm2*gvl.z),fast_tanh(nm2*gvl.w));

  g_sAV[pbase]   = split_u2(AV.x, AV.y);
  g_sAV[pbase+1] = split_u2(AV.z, AV.w);
  g_sAL[pbase]   = split_u2(AL.x, AL.y);
  g_sAL[pbase+1] = split_u2(AL.z, AL.w);
  g_sVL[pbase]   = split_u2(VL.x, VL.y);
  g_sVL[pbase+1] = split_u2(VL.z, VL.w);

  float4 bi = make_float4(AV.x+AL.x+VL.x, AV.y+AL.y+VL.y, AV.z+AL.z+VL.z, AV.w+AL.w+VL.w);
  g_sBi[pbase]   = split_u2(bi.x, bi.y);
  g_sBi[pbase+1] = split_u2(bi.z, bi.w);
}

// ---------------- K6: fused 3-layer head (tri summed inline, occ 2) ----------------
// smem: 0 b1s | 256 b2s | 512 b3s | 1024 W1p(49152) | 50176 W2p(8192) | 58368 W3p(16384) = 74752
#define SMEM_K6_REQ 74752

__global__ __launch_bounds__(256,2) void k6_tc(
    const float* __restrict__ b1, const float* __restrict__ b2,
    const float* __restrict__ b3, float* __restrict__ out)
{
  float* b1s = (float*)(smem_raw);
  float* b2s = (float*)(smem_raw + 256);
  float* b3s = (float*)(smem_raw + 512);
  uint2* W1p = (uint2*)(smem_raw + 1024);
  uint2* W2p = (uint2*)(smem_raw + 50176);
  uint2* W3p = (uint2*)(smem_raw + 58368);

  int tid = threadIdx.x;
  int row0 = blockIdx.x * 128;

  {
    uint4* d1 = (uint4*)W1p; const uint4* s1 = (const uint4*)g_llW1p;
    #pragma unroll
    for (int i = tid; i < 3072; i += 256) d1[i] = s1[i];
    uint4* d2 = (uint4*)W2p; const uint4* s2 = (const uint4*)g_llW2p;
    #pragma unroll
    for (int i = tid; i < 512; i += 256) d2[i] = s2[i];
    uint4* d3 = (uint4*)W3p; const uint4* s3 = (const uint4*)g_llW3p;
    #pragma unroll
    for (int i = tid; i < 1024; i += 256) d3[i] = s3[i];
  }
  if (tid < 64)  b1s[tid] = b1[tid];
  if (tid < 64)  b2s[tid] = b2[tid];
  if (tid < 128) b3s[tid] = b3[tid];
  __syncthreads();

  int w = tid >> 5, lane = tid & 31;
  int g = lane >> 2, tg = lane & 3;
  int r0 = row0 + w*16 + g;
  int r1 = r0 + 8;

  // -------- layer 1: fusion[128x384] @ W1[384x64] --------
  float acc[8][4];
  #pragma unroll
  for (int i=0;i<8;i++){ acc[i][0]=0.f; acc[i][1]=0.f; acc[i][2]=0.f; acc[i][3]=0.f; }

  #pragma unroll 1
  for (int kk = 0; kk < 24; kk++){
    int ch = kk >> 3;
    uint32_t ah[4], al[4];
    if (ch < 2){
      const uint2* sp = (ch == 0) ? g_sUni : g_sBi;
      int pi = (kk & 7)*8 + tg;
      const uint2* p0 = sp + (size_t)r0*64 + pi;
      const uint2* p1 = sp + (size_t)r1*64 + pi;
      uint2 u00 = p0[0], u01 = p0[4];
      uint2 u10 = p1[0], u11 = p1[4];
      ah[0]=u00.x; al[0]=u00.y;
      ah[1]=u10.x; al[1]=u10.y;
      ah[2]=u01.x; al[2]=u01.y;
      ah[3]=u11.x; al[3]=u11.y;
    } else {
      int cc = (kk & 7)*16 + tg*2;
      size_t o0 = (size_t)r0*DD + cc;
      size_t o1 = (size_t)r1*DD + cc;
      float2 v00 = *(const float2*)(g_G2 + o0);
      float2 v01 = *(const float2*)(g_G2 + o0 + 8);
      float2 v10 = *(const float2*)(g_G2 + o1);
      float2 v11 = *(const float2*)(g_G2 + o1 + 8);
      #pragma unroll
      for (int p = 1; p < 6; p++){
        size_t po = (size_t)p*SLOT;
        float2 q;
        q = *(const float2*)(g_G2 + po + o0);     v00.x+=q.x; v00.y+=q.y;
        q = *(const float2*)(g_G2 + po + o0 + 8); v01.x+=q.x; v01.y+=q.y;
        q = *(const float2*)(g_G2 + po + o1);     v10.x+=q.x; v10.y+=q.y;
        q = *(const float2*)(g_G2 + po + o1 + 8); v11.x+=q.x; v11.y+=q.y;
      }
      split_pack2(v00.x, v00.y, ah[0], al[0]);
      split_pack2(v10.x, v10.y, ah[1], al[1]);
      split_pack2(v01.x, v01.y, ah[2], al[2]);
      split_pack2(v11.x, v11.y, ah[3], al[3]);
    }
    const uint2* bp = W1p + kk*256 + lane;
    #pragma unroll
    for (int nt = 0; nt < 8; nt++){
      uint2 B = bp[nt*32];
      MMA(acc[nt], ah, B.x, B.y);
      MMA(acc[nt], al, B.x, B.y);
    }
  }

  uint32_t hh[4][4], hl[4][4];
  #pragma unroll
  for (int kt = 0; kt < 4; kt++){
    float* q0 = acc[2*kt];
    float* q1 = acc[2*kt+1];
    int c0 = kt*16 + tg*2;
    float bA = b1s[c0], bB = b1s[c0+1], bC = b1s[c0+8], bD = b1s[c0+9];
    split_pack2(fast_tanh(q0[0]+bA), fast_tanh(q0[1]+bB), hh[kt][0], hl[kt][0]);
    split_pack2(fast_tanh(q0[2]+bA), fast_tanh(q0[3]+bB), hh[kt][1], hl[kt][1]);
    split_pack2(fast_tanh(q1[0]+bC), fast_tanh(q1[1]+bD), hh[kt][2], hl[kt][2]);
    split_pack2(fast_tanh(q1[2]+bC), fast_tanh(q1[3]+bD), hh[kt][3], hl[kt][3]);
  }

  // -------- layer 2: H1[128x64] @ W2[64x64] --------
  #pragma unroll
  for (int i=0;i<8;i++){ acc[i][0]=0.f; acc[i][1]=0.f; acc[i][2]=0.f; acc[i][3]=0.f; }
  #pragma unroll
  for (int nt = 0; nt < 8; nt++){
    #pragma unroll
    for (int kt = 0; kt < 4; kt++){
      uint2 B = W2p[kt*256 + nt*32 + lane];
      MMA(acc[nt], hh[kt], B.x, B.y);
      MMA(acc[nt], hl[kt], B.x, B.y);
    }
  }
  #pragma unroll
  for (int kt = 0; kt < 4; kt++){
    float* q0 = acc[2*kt];
    float* q1 = acc[2*kt+1];
    int c0 = kt*16 + tg*2;
    float bA = b2s[c0], bB = b2s[c0+1], bC = b2s[c0+8], bD = b2s[c0+9];
    split_pack2(fast_tanh(q0[0]+bA), fast_tanh(q0[1]+bB), hh[kt][0], hl[kt][0]);
    split_pack2(fast_tanh(q0[2]+bA), fast_tanh(q0[3]+bB), hh[kt][1], hl[kt][1]);
    split_pack2(fast_tanh(q1[0]+bC), fast_tanh(q1[1]+bD), hh[kt][2], hl[kt][2]);
    split_pack2(fast_tanh(q1[2]+bC), fast_tanh(q1[3]+bD), hh[kt][3], hl[kt][3]);
  }

  // -------- layer 3: H2[128x64] @ W3[64x128] --------
  #pragma unroll 1
  for (int nh = 0; nh < 2; nh++){
    float acc2[8][4];
    #pragma unroll
    for (int i=0;i<8;i++){ acc2[i][0]=0.f; acc2[i][1]=0.f; acc2[i][2]=0.f; acc2[i][3]=0.f; }
    const uint2* bp3 = W3p + nh*1024 + lane;
    #pragma unroll
    for (int nt = 0; nt < 8; nt++){
      #pragma unroll
      for (int kt = 0; kt < 4; kt++){
        uint2 B = bp3[kt*256 + nt*32];
        MMA(acc2[nt], hh[kt], B.x, B.y);
        MMA(acc2[nt], hl[kt], B.x, B.y);
      }
    }
    #pragma unroll
    for (int nt = 0; nt < 8; nt++){
      int col = (nh*8+nt)*8 + tg*2;
      float v0 = fast_tanh(acc2[nt][0] + b3s[col]);
      float v1 = fast_tanh(acc2[nt][1] + b3s[col+1]);
      float v2 = fast_tanh(acc2[nt][2] + b3s[col]);
      float v3 = fast_tanh(acc2[nt][3] + b3s[col+1]);
      *(float2*)(out + (size_t)r0*DD + col) = make_float2(v0, v1);
      *(float2*)(out + (size_t)r1*DD + col) = make_float2(v2, v3);
    }
  }
}

// ---------------- launch ----------------
extern "C" void kernel_launch(void* const* d_in, const int* in_sizes, int n_in,
                              void* d_out, int out_size)
{
  (void)in_sizes; (void)n_in; (void)out_size;
  const float* L     = (const float*)d_in[0];
  const float* A     = (const float*)d_in[1];
  const float* V     = (const float*)d_in[2];
  const float* attw  = (const float*)d_in[3];
  const float* attb  = (const float*)d_in[4];
  const float* gfw1  = (const float*)d_in[5];
  const float* gfb1  = (const float*)d_in[6];
  const float* gfw2  = (const float*)d_in[7];
  const float* gfb2  = (const float*)d_in[8];
  const float* gf2w1 = (const float*)d_in[9];
  const float* gf2b1 = (const float*)d_in[10];
  const float* gf2w2 = (const float*)d_in[11];
  const float* gf2b2 = (const float*)d_in[12];
  const float* llw1  = (const float*)d_in[13];
  const float* llb1  = (const float*)d_in[14];
  const float* llw2  = (const float*)d_in[15];
  const float* llb2  = (const float*)d_in[16];
  const float* llw3  = (const float*)d_in[17];
  const float* llb3  = (const float*)d_in[18];
  float* out = (float*)d_out;

  cudaFuncSetAttribute(k2_tc, cudaFuncAttributeMaxDynamicSharedMemorySize, SMEM_MLP_REQ);
  cudaFuncSetAttribute(k4_tc, cudaFuncAttributeMaxDynamicSharedMemorySize, SMEM_MLP_REQ);
  cudaFuncSetAttribute(k6_tc, cudaFuncAttributeMaxDynamicSharedMemorySize, SMEM_K6_REQ);

  k0_conv<<<dim3(36,3), 256>>>(gfw1, gfw2, gf2w1, gf2w2, llw1, llw2, llw3);
  k1_pre<<<NB/8, 256>>>(L, A, V, attw, attb);
  k2_tc<<<dim3(512,3), 256, SMEM_MLP_REQ>>>(gfb1, gfb2);
  k3_mid<<<NB/8, 256>>>();
  k4_tc<<<dim3(512,6), 256, SMEM_MLP_REQ>>>(gf2b1, gf2b2);
  k6_tc<<<512, 256, SMEM_K6_REQ>>>(llb1, llb2, llb3, out);
}

// round 16
// speedup vs baseline: 1.3643x; 1.3643x over previous
#include <cuda_runtime.h>
#include <cuda_fp16.h>
#include <cstdint>

// R16: A/A re-bench of the occ-2 fp16 kernel (round 15 code, unchanged).
// Round 15 landed on the throttled clock state (k3 canary 96us/3155GB/s, the
// same state as rounds 8/10); iso-clock estimate ~421us would be the best yet.
// Re-benching unchanged to get a fast-state measurement before committing.

#define NB 65536
#define DD 128
#define SLOT (NB*DD)
#define PSLOT (NB*64)

// ---------------- scratch ----------------
__device__ uint2 g_sPa[PSLOT];
__device__ uint2 g_sPv[PSLOT];
__device__ uint2 g_sPl[PSLOT];
__device__ uint2 g_sUni[PSLOT];
__device__ uint2 g_sBi[PSLOT];
__device__ uint2 g_sAV[PSLOT];
__device__ uint2 g_sAL[PSLOT];
__device__ uint2 g_sVL[PSLOT];
__device__ float g_G[3*SLOT];    // gav/gal/gvl fp32 (k2 -> k3)
__device__ float g_G2[6*SLOT];   // gf2 outputs fp32 (k4 -> k6)
__device__ float g_s[NB*16];

// packed 8B single-fp16 B-fragments: {b0, b1} per (k-step, n-tile, lane)
__device__ __align__(16) uint2 g_gfW1p[2][4096];
__device__ __align__(16) uint2 g_gfW2p[2][2048];
__device__ __align__(16) uint2 g_llW1p[6144];
__device__ __align__(16) uint2 g_llW2p[1024];
__device__ __align__(16) uint2 g_llW3p[2048];

extern __shared__ char smem_raw[];

// ---------------- helpers ----------------
__device__ __forceinline__ float wsum(float x){
  #pragma unroll
  for (int o=16;o;o>>=1) x += __shfl_xor_sync(0xffffffffu, x, o);
  return x;
}
__device__ __forceinline__ float wmax(float x){
  #pragma unroll
  for (int o=16;o;o>>=1) x = fmaxf(x, __shfl_xor_sync(0xffffffffu, x, o));
  return x;
}
__device__ __forceinline__ float dot4(float4 a, float4 b){
  return a.x*b.x + a.y*b.y + a.z*b.z + a.w*b.w;
}
__device__ __forceinline__ float max4(float4 a){ return fmaxf(fmaxf(a.x,a.y),fmaxf(a.z,a.w)); }
__device__ __forceinline__ float sum4(float4 a){ return a.x+a.y+a.z+a.w; }

__device__ __forceinline__ float fast_exp(float x){
  float e; asm("ex2.approx.f32 %0, %1;" : "=f"(e) : "f"(x*1.4426950408889634f));
  return e;
}
__device__ __forceinline__ float fast_tanh(float x){
  float e; asm("ex2.approx.f32 %0, %1;" : "=f"(e) : "f"(x*2.8853900817779268f));
  float r; asm("rcp.approx.f32 %0, %1;" : "=f"(r) : "f"(e+1.0f));
  return fmaf(-2.0f, r, 1.0f);
}

__device__ __forceinline__ uint32_t pack_h2(float x, float y){
  __half hx = __float2half_rn(x), hy = __float2half_rn(y);
  return (uint32_t)__half_as_ushort(hx) | ((uint32_t)__half_as_ushort(hy) << 16);
}
// fp16 split: hi = fp16(x), lo = fp16(x - hi)
__device__ __forceinline__ void split_pack2(float x, float y, uint32_t &h, uint32_t &l){
  __half hx = __float2half_rn(x), hy = __float2half_rn(y);
  float rx = x - __half2float(hx);
  float ry = y - __half2float(hy);
  h = (uint32_t)__half_as_ushort(hx) | ((uint32_t)__half_as_ushort(hy) << 16);
  l = pack_h2(rx, ry);
}
__device__ __forceinline__ uint2 split_u2(float x, float y){
  uint32_t h, l; split_pack2(x, y, h, l); return make_uint2(h, l);
}
__device__ __forceinline__ float2 unsplit(uint2 u){
  float2 a = __half22float2(*reinterpret_cast<__half2*>(&u.x));
  float2 b = __half22float2(*reinterpret_cast<__half2*>(&u.y));
  return make_float2(a.x + b.x, a.y + b.y);
}
__device__ __forceinline__ uint2 make_frag(float e0, float e1, float e2, float e3){
  return make_uint2(pack_h2(e0, e1), pack_h2(e2, e3));
}

#define MMA(c, a, bb0, bb1) \
  asm volatile("mma.sync.aligned.m16n8k16.row.col.f32.f16.f16.f32 " \
    "{%0,%1,%2,%3}, {%4,%5,%6,%7}, {%8,%9}, {%0,%1,%2,%3};" \
    : "+f"((c)[0]),"+f"((c)[1]),"+f"((c)[2]),"+f"((c)[3]) \
    : "r"((a)[0]),"r"((a)[1]),"r"((a)[2]),"r"((a)[3]), "r"(bb0),"r"(bb1))

__device__ __forceinline__ float lrelu(float x){ return (x > 0.f) ? x : 0.2f*x; }

// ---------------- K0: weight -> packed single-fp16 fragments ----------------
__global__ __launch_bounds__(256) void k0_conv(
    const float* __restrict__ gw1,  const float* __restrict__ gw2,
    const float* __restrict__ g2w1, const float* __restrict__ g2w2,
    const float* __restrict__ lw1,  const float* __restrict__ lw2,
    const float* __restrict__ lw3)
{
  int y = blockIdx.y;
  int e = blockIdx.x*256 + threadIdx.x;
  if (y < 2){
    if (e < 4096){
      int kk = e>>8, rem = e&255, nt = rem>>5, lane = rem&31, g = lane>>2, tg = lane&3;
      int n = nt*8+g, k = kk*16+tg*2;
      const float* w1 = y ? g2w1 : gw1;   // [256,64]
      g_gfW1p[y][e] = make_frag(w1[k*64+n], w1[(k+1)*64+n], w1[(k+8)*64+n], w1[(k+9)*64+n]);
    } else if (e < 6144){
      int f = e-4096;
      int q = f>>8, rem = f&255, nt = rem>>5, lane = rem&31, g = lane>>2, tg = lane&3;
      int nh = q>>2, kt = q&3;
      int n = (nh*8+nt)*8+g, k = kt*16+tg*2;
      const float* w2 = y ? g2w2 : gw2;   // [64,128]
      g_gfW2p[y][f] = make_frag(w2[k*128+n], w2[(k+1)*128+n], w2[(k+8)*128+n], w2[(k+9)*128+n]);
    }
  } else {
    if (e < 6144){
      int kk = e>>8, rem = e&255, nt = rem>>5, lane = rem&31, g = lane>>2, tg = lane&3;
      int n = nt*8+g, k = kk*16+tg*2;     // lw1 [384,64]
      g_llW1p[e] = make_frag(lw1[k*64+n], lw1[(k+1)*64+n], lw1[(k+8)*64+n], lw1[(k+9)*64+n]);
    } else if (e < 7168){
      int f = e-6144;
      int kt = f>>8, rem = f&255, nt = rem>>5, lane = rem&31, g = lane>>2, tg = lane&3;
      int n = nt*8+g, k = kt*16+tg*2;     // lw2 [64,64]
      g_llW2p[f] = make_frag(lw2[k*64+n], lw2[(k+1)*64+n], lw2[(k+8)*64+n], lw2[(k+9)*64+n]);
    } else if (e < 9216){
      int f = e-7168;
      int q = f>>8, rem = f&255, nt = rem>>5, lane = rem&31, g = lane>>2, tg = lane&3;
      int nh = q>>2, kt = q&3;
      int n = (nh*8+nt)*8+g, k = kt*16+tg*2;  // lw3 [64,128]
      g_llW3p[f] = make_frag(lw3[k*128+n], lw3[(k+1)*128+n], lw3[(k+8)*128+n], lw3[(k+9)*128+n]);
    }
  }
}

// ---------------- K1: rowwise pre ----------------
__global__ __launch_bounds__(256) void k1_pre(
    const float* __restrict__ L, const float* __restrict__ A,
    const float* __restrict__ V, const float* __restrict__ attw,
    const float* __restrict__ attb)
{
  int gw   = (int)((blockIdx.x*blockDim.x + threadIdx.x) >> 5);
  int lane = threadIdx.x & 31;
  size_t base = (size_t)gw*DD + lane*4;
  size_t pbase = (size_t)gw*64 + lane*2;

  float4 av = *(const float4*)(A+base);
  float4 vv = *(const float4*)(V+base);
  float4 lv = *(const float4*)(L+base);
  float4 wv = *(const float4*)(attw + lane*4);
  float bb = attb[0];

  float sa = fast_tanh(wsum(dot4(av,wv)) + bb);
  float sv = fast_tanh(wsum(dot4(vv,wv)) + bb);
  float sl = fast_tanh(wsum(dot4(lv,wv)) + bb);

  float4 u;
  u.x = (sa*av.x + sv*vv.x + sl*lv.x)*(1.0f/3.0f);
  u.y = (sa*av.y + sv*vv.y + sl*lv.y)*(1.0f/3.0f);
  u.z = (sa*av.z + sv*vv.z + sl*lv.z)*(1.0f/3.0f);
  u.w = (sa*av.w + sv*vv.w + sl*lv.w)*(1.0f/3.0f);
  g_sUni[pbase]   = split_u2(u.x, u.y);
  g_sUni[pbase+1] = split_u2(u.z, u.w);

  float m = wmax(max4(av));
  float4 pa = make_float4(fast_exp(av.x-m),fast_exp(av.y-m),fast_exp(av.z-m),fast_exp(av.w-m));
  float inv = 1.0f/wsum(sum4(pa));
  pa.x*=inv; pa.y*=inv; pa.z*=inv; pa.w*=inv;
  m = wmax(max4(vv));
  float4 pv = make_float4(fast_exp(vv.x-m),fast_exp(vv.y-m),fast_exp(vv.z-m),fast_exp(vv.w-m));
  inv = 1.0f/wsum(sum4(pv));
  pv.x*=inv; pv.y*=inv; pv.z*=inv; pv.w*=inv;
  m = wmax(max4(lv));
  float4 pl = make_float4(fast_exp(lv.x-m),fast_exp(lv.y-m),fast_exp(lv.z-m),fast_exp(lv.w-m));
  inv = 1.0f/wsum(sum4(pl));
  pl.x*=inv; pl.y*=inv; pl.z*=inv; pl.w*=inv;

  g_sPa[pbase]   = split_u2(pa.x, pa.y);
  g_sPa[pbase+1] = split_u2(pa.z, pa.w);
  g_sPv[pbase]   = split_u2(pv.x, pv.y);
  g_sPv[pbase+1] = split_u2(pv.z, pv.w);
  g_sPl[pbase]   = split_u2(pl.x, pl.y);
  g_sPl[pbase+1] = split_u2(pl.z, pl.w);

  float dav = wsum(dot4(pa,pv));
  float dal = wsum(dot4(pa,pl));
  float dvl = wsum(dot4(pv,pl));

  float sav = (sa+sv)/(dav+0.5f);
  float sal = (sa+sl)/(dal+0.5f);
  float svl = (sl+sv)/(dvl+0.5f);

  float m3 = fmaxf(sav,fmaxf(sal,svl));
  float e0 = fast_exp(sav-m3), e1 = fast_exp(sal-m3), e2 = fast_exp(svl-m3);
  float r3 = 1.0f/(e0+e1+e2);

  if (lane==0){
    float* s = g_s + (size_t)gw*16;
    s[0]=sa; s[1]=sv; s[2]=sl;
    s[3]=sav; s[4]=sal; s[5]=svl;
    s[6]=e0*r3; s[7]=e1*r3; s[8]=e2*r3;
  }
}

// ---------------- 2-layer MLP body (packed fp16 weights in smem, occ 2) ----------------
// smem: 0 b1s(256B) | 256 b2s(512B) | 1024 W1p(32768) | 33792 W2p(16384) = 50176
#define SMEM_MLP_REQ 50176

__device__ __forceinline__ void mlp2_body(
    const uint2* __restrict__ x1, const uint2* __restrict__ x2,
    float* __restrict__ outp, int row0, int n2slot)
{
  const float* b1s = (const float*)(smem_raw);
  const float* b2s = (const float*)(smem_raw + 256);
  const uint2* W1p = (const uint2*)(smem_raw + 1024);
  const uint2* W2p = (const uint2*)(smem_raw + 33792);

  int tid = threadIdx.x;
  int w = tid >> 5, lane = tid & 31;
  int g = lane >> 2, tg = lane & 3;
  int r0 = row0 + w*16 + g;
  int r1 = r0 + 8;

  // -------- stage 1: concat(x1,x2)[128x256] @ W1 --------
  float acc[8][4];
  #pragma unroll
  for (int i=0;i<8;i++){ acc[i][0]=0.f; acc[i][1]=0.f; acc[i][2]=0.f; acc[i][3]=0.f; }

  uint2 cu0, cu1, cu2, cu3;
  {
    const uint2* p0 = x1 + (size_t)r0*64 + tg;
    const uint2* p1 = x1 + (size_t)r1*64 + tg;
    cu0 = p0[0]; cu1 = p1[0]; cu2 = p0[4]; cu3 = p1[4];
  }
  #pragma unroll 1
  for (int kk = 0; kk < 16; kk++){
    uint32_t ah[4], al[4];
    ah[0]=cu0.x; al[0]=cu0.y;
    ah[1]=cu1.x; al[1]=cu1.y;
    ah[2]=cu2.x; al[2]=cu2.y;
    ah[3]=cu3.x; al[3]=cu3.y;
    if (kk < 15){
      int k2i = kk + 1;
      const uint2* s2 = (k2i < 8) ? x1 : x2;
      int pi2 = (k2i & 7)*8 + tg;
      const uint2* p0 = s2 + (size_t)r0*64 + pi2;
      const uint2* p1 = s2 + (size_t)r1*64 + pi2;
      cu0 = p0[0]; cu1 = p1[0]; cu2 = p0[4]; cu3 = p1[4];
    }
    const uint2* bp = W1p + kk*256 + lane;
    #pragma unroll
    for (int nt = 0; nt < 8; nt++){
      uint2 B = bp[nt*32];
      MMA(acc[nt], ah, B.x, B.y);
      MMA(acc[nt], al, B.x, B.y);
    }
  }

  // -------- H = lrelu(acc + b1) -> frags --------
  uint32_t hh[4][4], hl[4][4];
  #pragma unroll
  for (int kt = 0; kt < 4; kt++){
    float* t0 = acc[2*kt];
    float* t1 = acc[2*kt+1];
    int c0 = kt*16 + tg*2;
    float bA = b1s[c0], bB = b1s[c0+1], bC = b1s[c0+8], bD = b1s[c0+9];
    split_pack2(lrelu(t0[0]+bA), lrelu(t0[1]+bB), hh[kt][0], hl[kt][0]);
    split_pack2(lrelu(t0[2]+bA), lrelu(t0[3]+bB), hh[kt][1], hl[kt][1]);
    split_pack2(lrelu(t1[0]+bC), lrelu(t1[1]+bD), hh[kt][2], hl[kt][2]);
    split_pack2(lrelu(t1[2]+bC), lrelu(t1[3]+bD), hh[kt][3], hl[kt][3]);
  }

  // -------- stage 2: H[128x64] @ W2[64x128] --------
  float scv0 = 0.f, scv1 = 0.f;
  if (n2slot >= 0){
    scv0 = g_s[(size_t)r0*16 + n2slot];
    scv1 = g_s[(size_t)r1*16 + n2slot];
  }
  #pragma unroll 1
  for (int nh = 0; nh < 2; nh++){
    float acc2[8][4];
    #pragma unroll
    for (int i=0;i<8;i++){ acc2[i][0]=0.f; acc2[i][1]=0.f; acc2[i][2]=0.f; acc2[i][3]=0.f; }
    const uint2* bp2 = W2p + nh*1024 + lane;
    #pragma unroll
    for (int nt = 0; nt < 8; nt++){
      #pragma unroll
      for (int kt = 0; kt < 4; kt++){
        uint2 B = bp2[kt*256 + nt*32];
        MMA(acc2[nt], hh[kt], B.x, B.y);
        MMA(acc2[nt], hl[kt], B.x, B.y);
      }
    }
    #pragma unroll
    for (int nt = 0; nt < 8; nt++){
      int col = (nh*8+nt)*8 + tg*2;
      float v0 = fast_tanh(acc2[nt][0] + b2s[col]);
      float v1 = fast_tanh(acc2[nt][1] + b2s[col+1]);
      float v2 = fast_tanh(acc2[nt][2] + b2s[col]);
      float v3 = fast_tanh(acc2[nt][3] + b2s[col+1]);
      if (n2slot >= 0){
        v0 = fast_tanh(scv0*v0); v1 = fast_tanh(scv0*v1);
        v2 = fast_tanh(scv1*v2); v3 = fast_tanh(scv1*v3);
      }
      *(float2*)(outp + (size_t)r0*DD + col) = make_float2(v0, v1);
      *(float2*)(outp + (size_t)r1*DD + col) = make_float2(v2, v3);
    }
  }
}

__device__ __forceinline__ void stage_mlp_weights(int set,
    const float* __restrict__ b1, const float* __restrict__ b2)
{
  float* b1s = (float*)(smem_raw);
  float* b2s = (float*)(smem_raw + 256);
  uint4* dW1 = (uint4*)(smem_raw + 1024);
  uint4* dW2 = (uint4*)(smem_raw + 33792);
  int tid = threadIdx.x;
  const uint4* s1 = (const uint4*)g_gfW1p[set];
  const uint4* s2 = (const uint4*)g_gfW2p[set];
  #pragma unroll
  for (int i = tid; i < 2048; i += 256) dW1[i] = s1[i];
  #pragma unroll
  for (int i = tid; i < 1024; i += 256) dW2[i] = s2[i];
  if (tid < 64)  b1s[tid] = b1[tid];
  if (tid < 128) b2s[tid] = b2[tid];
  __syncthreads();
}

// ---------------- K2 / K4 (occ 2) ----------------
__global__ __launch_bounds__(256,2) void k2_tc(const float* __restrict__ b1, const float* __restrict__ b2)
{
  stage_mlp_weights(0, b1, b2);
  const uint2 *x1, *x2;
  int p = blockIdx.y;
  if (p==0){ x1=g_sPa; x2=g_sPv; }
  else if (p==1){ x1=g_sPa; x2=g_sPl; }
  else { x1=g_sPv; x2=g_sPl; }
  mlp2_body(x1, x2, g_G + (size_t)p*SLOT, blockIdx.x*128, -1);
}

__global__ __launch_bounds__(256,2) void k4_tc(const float* __restrict__ b1, const float* __restrict__ b2)
{
  stage_mlp_weights(1, b1, b2);
  const uint2 *x1, *x2;
  int p = blockIdx.y;
  switch(p){
    case 0: x1=g_sAV; x2=g_sVL; break;
    case 1: x1=g_sAV; x2=g_sAL; break;
    case 2: x1=g_sVL; x2=g_sAL; break;
    case 3: x1=g_sAV; x2=g_sPl; break;
    case 4: x1=g_sAL; x2=g_sPv; break;
    default:x1=g_sVL; x2=g_sPa; break;
  }
  mlp2_body(x1, x2, g_G2 + (size_t)p*SLOT, blockIdx.x*128, 9+p);
}

// ---------------- K3: rowwise mid ----------------
__global__ __launch_bounds__(256) void k3_mid()
{
  int gw   = (int)((blockIdx.x*blockDim.x + threadIdx.x) >> 5);
  int lane = threadIdx.x & 31;
  size_t base = (size_t)gw*DD + lane*4;
  size_t pbase = (size_t)gw*64 + lane*2;

  float4 gav = *(const float4*)(g_G + base);
  float4 gal = *(const float4*)(g_G + (size_t)SLOT + base);
  float4 gvl = *(const float4*)(g_G + 2*(size_t)SLOT + base);

  float2 t0, t1;
  t0 = unsplit(g_sPa[pbase]); t1 = unsplit(g_sPa[pbase+1]);
  float4 pa = make_float4(t0.x, t0.y, t1.x, t1.y);
  t0 = unsplit(g_sPv[pbase]); t1 = unsplit(g_sPv[pbase+1]);
  float4 pv = make_float4(t0.x, t0.y, t1.x, t1.y);
  t0 = unsplit(g_sPl[pbase]); t1 = unsplit(g_sPl[pbase+1]);
  float4 pl = make_float4(t0.x, t0.y, t1.x, t1.y);

  float m, inv;
  m = wmax(max4(gav));
  float4 A2 = make_float4(fast_exp(gav.x-m),fast_exp(gav.y-m),fast_exp(gav.z-m),fast_exp(gav.w-m));
  inv = 1.0f/wsum(sum4(A2)); A2.x*=inv; A2.y*=inv; A2.z*=inv; A2.w*=inv;
  m = wmax(max4(gal));
  float4 L2 = make_float4(fast_exp(gal.x-m),fast_exp(gal.y-m),fast_exp(gal.z-m),fast_exp(gal.w-m));
  inv = 1.0f/wsum(sum4(L2)); L2.x*=inv; L2.y*=inv; L2.z*=inv; L2.w*=inv;
  m = wmax(max4(gvl));
  float4 V2 = make_float4(fast_exp(gvl.x-m),fast_exp(gvl.y-m),fast_exp(gvl.z-m),fast_exp(gvl.w-m));
  inv = 1.0f/wsum(sum4(V2)); V2.x*=inv; V2.y*=inv; V2.z*=inv; V2.w*=inv;

  float d0 = wsum(dot4(A2,V2));
  float d1 = wsum(dot4(A2,L2));
  float d2 = wsum(dot4(L2,V2));
  float d3 = wsum(dot4(A2,pl));
  float d4 = wsum(dot4(L2,pv));
  float d5 = wsum(dot4(V2,pa));

  const float* s = g_s + (size_t)gw*16;
  float sa1=s[0], sv1=s[1], sl1=s[2], sav=s[3], sal=s[4], svl=s[5];
  float nm0=s[6], nm1=s[7], nm2=s[8];

  float e0=(sav+svl)/(d0+0.5f);
  float e1=(sav+sal)/(d1+0.5f);
  float e2=(sal+svl)/(d2+0.5f);
  float e3=(sav+sl1)/(d3+0.5f);
  float e4=(sal+sv1)/(d4+0.5f);
  float e5=(sa1+svl)/(d5+0.5f);
  float mm = fmaxf(fmaxf(fmaxf(e0,e1),fmaxf(e2,e3)),fmaxf(e4,e5));
  float x0=fast_exp(e0-mm),x1=fast_exp(e1-mm),x2=fast_exp(e2-mm);
  float x3=fast_exp(e3-mm),x4=fast_exp(e4-mm),x5=fast_exp(e5-mm);
  float ri = 1.0f/(x0+x1+x2+x3+x4+x5);
  if (lane==0){
    float* sw = g_s + (size_t)gw*16;
    sw[9]=x0*ri; sw[10]=x1*ri; sw[11]=x2*ri; sw[12]=x3*ri; sw[13]=x4*ri; sw[14]=x5*ri;
  }

  float4 AV = make_float4(fast_tanh(nm0*gav.x),fast_tanh(nm0*gav.y),fast_tanh(nm0*gav.z),fast_tanh(nm0*gav.w));
  float4 AL = make_float4(fast_tanh(nm1*gal.x),fast_tanh(nm1*gal.y),fast_tanh(nm1*gal.z),fast_tanh(nm1*gal.w));
  float4 VL = make_float4(fast_tanh(nm2*gvl.x),fast_tanh(nm2*gvl.y),fast_tanh(nm2*gvl.z),fast_tanh(nm2*gvl.w));

  g_sAV[pbase]   = split_u2(AV.x, AV.y);
  g_sAV[pbase+1] = split_u2(AV.z, AV.w);
  g_sAL[pbase]   = split_u2(AL.x, AL.y);
  g_sAL[pbase+1] = split_u2(AL.z, AL.w);
  g_sVL[pbase]   = split_u2(VL.x, VL.y);
  g_sVL[pbase+1] = split_u2(VL.z, VL.w);

  float4 bi = make_float4(AV.x+AL.x+VL.x, AV.y+AL.y+VL.y, AV.z+AL.z+VL.z, AV.w+AL.w+VL.w);
  g_sBi[pbase]   = split_u2(bi.x, bi.y);
  g_sBi[pbase+1] = split_u2(bi.z, bi.w);
}

// ---------------- K6: fused 3-layer head (tri summed inline, occ 2) ----------------
// smem: 0 b1s | 256 b2s | 512 b3s | 1024 W1p(49152) | 50176 W2p(8192) | 58368 W3p(16384) = 74752
#define SMEM_K6_REQ 74752

__global__ __launch_bounds__(256,2) void k6_tc(
    const float* __restrict__ b1, const float* __restrict__ b2,
    const float* __restrict__ b3, float* __restrict__ out)
{
  float* b1s = (float*)(smem_raw);
  float* b2s = (float*)(smem_raw + 256);
  float* b3s = (float*)(smem_raw + 512);
  uint2* W1p = (uint2*)(smem_raw + 1024);
  uint2* W2p = (uint2*)(smem_raw + 50176);
  uint2* W3p = (uint2*)(smem_raw + 58368);

  int tid = threadIdx.x;
  int row0 = blockIdx.x * 128;

  {
    uint4* d1 = (uint4*)W1p; const uint4* s1 = (const uint4*)g_llW1p;
    #pragma unroll
    for (int i = tid; i < 3072; i += 256) d1[i] = s1[i];
    uint4* d2 = (uint4*)W2p; const uint4* s2 = (const uint4*)g_llW2p;
    #pragma unroll
    for (int i = tid; i < 512; i += 256) d2[i] = s2[i];
    uint4* d3 = (uint4*)W3p; const uint4* s3 = (const uint4*)g_llW3p;
    #pragma unroll
    for (int i = tid; i < 1024; i += 256) d3[i] = s3[i];
  }
  if (tid < 64)  b1s[tid] = b1[tid];
  if (tid < 64)  b2s[tid] = b2[tid];
  if (tid < 128) b3s[tid] = b3[tid];
  __syncthreads();

  int w = tid >> 5, lane = tid & 31;
  int g = lane >> 2, tg = lane & 3;
  int r0 = row0 + w*16 + g;
  int r1 = r0 + 8;

  // -------- layer 1: fusion[128x384] @ W1[384x64] --------
  float acc[8][4];
  #pragma unroll
  for (int i=0;i<8;i++){ acc[i][0]=0.f; acc[i][1]=0.f; acc[i][2]=0.f; acc[i][3]=0.f; }

  #pragma unroll 1
  for (int kk = 0; kk < 24; kk++){
    int ch = kk >> 3;
    uint32_t ah[4], al[4];
    if (ch < 2){
      const uint2* sp = (ch == 0) ? g_sUni : g_sBi;
      int pi = (kk & 7)*8 + tg;
      const uint2* p0 = sp + (size_t)r0*64 + pi;
      const uint2* p1 = sp + (size_t)r1*64 + pi;
      uint2 u00 = p0[0], u01 = p0[4];
      uint2 u10 = p1[0], u11 = p1[4];
      ah[0]=u00.x; al[0]=u00.y;
      ah[1]=u10.x; al[1]=u10.y;
      ah[2]=u01.x; al[2]=u01.y;
      ah[3]=u11.x; al[3]=u11.y;
    } else {
      int cc = (kk & 7)*16 + tg*2;
      size_t o0 = (size_t)r0*DD + cc;
      size_t o1 = (size_t)r1*DD + cc;
      float2 v00 = *(const float2*)(g_G2 + o0);
      float2 v01 = *(const float2*)(g_G2 + o0 + 8);
      float2 v10 = *(const float2*)(g_G2 + o1);
      float2 v11 = *(const float2*)(g_G2 + o1 + 8);
      #pragma unroll
      for (int p = 1; p < 6; p++){
        size_t po = (size_t)p*SLOT;
        float2 q;
        q = *(const float2*)(g_G2 + po + o0);     v00.x+=q.x; v00.y+=q.y;
        q = *(const float2*)(g_G2 + po + o0 + 8); v01.x+=q.x; v01.y+=q.y;
        q = *(const float2*)(g_G2 + po + o1);     v10.x+=q.x; v10.y+=q.y;
        q = *(const float2*)(g_G2 + po + o1 + 8); v11.x+=q.x; v11.y+=q.y;
      }
      split_pack2(v00.x, v00.y, ah[0], al[0]);
      split_pack2(v10.x, v10.y, ah[1], al[1]);
      split_pack2(v01.x, v01.y, ah[2], al[2]);
      split_pack2(v11.x, v11.y, ah[3], al[3]);
    }
    const uint2* bp = W1p + kk*256 + lane;
    #pragma unroll
    for (int nt = 0; nt < 8; nt++){
      uint2 B = bp[nt*32];
      MMA(acc[nt], ah, B.x, B.y);
      MMA(acc[nt], al, B.x, B.y);
    }
  }

  uint32_t hh[4][4], hl[4][4];
  #pragma unroll
  for (int kt = 0; kt < 4; kt++){
    float* q0 = acc[2*kt];
    float* q1 = acc[2*kt+1];
    int c0 = kt*16 + tg*2;
    float bA = b1s[c0], bB = b1s[c0+1], bC = b1s[c0+8], bD = b1s[c0+9];
    split_pack2(fast_tanh(q0[0]+bA), fast_tanh(q0[1]+bB), hh[kt][0], hl[kt][0]);
    split_pack2(fast_tanh(q0[2]+bA), fast_tanh(q0[3]+bB), hh[kt][1], hl[kt][1]);
    split_pack2(fast_tanh(q1[0]+bC), fast_tanh(q1[1]+bD), hh[kt][2], hl[kt][2]);
    split_pack2(fast_tanh(q1[2]+bC), fast_tanh(q1[3]+bD), hh[kt][3], hl[kt][3]);
  }

  // -------- layer 2: H1[128x64] @ W2[64x64] --------
  #pragma unroll
  for (int i=0;i<8;i++){ acc[i][0]=0.f; acc[i][1]=0.f; acc[i][2]=0.f; acc[i][3]=0.f; }
  #pragma unroll
  for (int nt = 0; nt < 8; nt++){
    #pragma unroll
    for (int kt = 0; kt < 4; kt++){
      uint2 B = W2p[kt*256 + nt*32 + lane];
      MMA(acc[nt], hh[kt], B.x, B.y);
      MMA(acc[nt], hl[kt], B.x, B.y);
    }
  }
  #pragma unroll
  for (int kt = 0; kt < 4; kt++){
    float* q0 = acc[2*kt];
    float* q1 = acc[2*kt+1];
    int c0 = kt*16 + tg*2;
    float bA = b2s[c0], bB = b2s[c0+1], bC = b2s[c0+8], bD = b2s[c0+9];
    split_pack2(fast_tanh(q0[0]+bA), fast_tanh(q0[1]+bB), hh[kt][0], hl[kt][0]);
    split_pack2(fast_tanh(q0[2]+bA), fast_tanh(q0[3]+bB), hh[kt][1], hl[kt][1]);
    split_pack2(fast_tanh(q1[0]+bC), fast_tanh(q1[1]+bD), hh[kt][2], hl[kt][2]);
    split_pack2(fast_tanh(q1[2]+bC), fast_tanh(q1[3]+bD), hh[kt][3], hl[kt][3]);
  }

  // -------- layer 3: H2[128x64] @ W3[64x128] --------
  #pragma unroll 1
  for (int nh = 0; nh < 2; nh++){
    float acc2[8][4];
    #pragma unroll
    for (int i=0;i<8;i++){ acc2[i][0]=0.f; acc2[i][1]=0.f; acc2[i][2]=0.f; acc2[i][3]=0.f; }
    const uint2* bp3 = W3p + nh*1024 + lane;
    #pragma unroll
    for (int nt = 0; nt < 8; nt++){
      #pragma unroll
      for (int kt = 0; kt < 4; kt++){
        uint2 B = bp3[kt*256 + nt*32];
        MMA(acc2[nt], hh[kt], B.x, B.y);
        MMA(acc2[nt], hl[kt], B.x, B.y);
      }
    }
    #pragma unroll
    for (int nt = 0; nt < 8; nt++){
      int col = (nh*8+nt)*8 + tg*2;
      float v0 = fast_tanh(acc2[nt][0] + b3s[col]);
      float v1 = fast_tanh(acc2[nt][1] + b3s[col+1]);
      float v2 = fast_tanh(acc2[nt][2] + b3s[col]);
      float v3 = fast_tanh(acc2[nt][3] + b3s[col+1]);
      *(float2*)(out + (size_t)r0*DD + col) = make_float2(v0, v1);
      *(float2*)(out + (size_t)r1*DD + col) = make_float2(v2, v3);
    }
  }
}

// ---------------- launch ----------------
extern "C" void kernel_launch(void* const* d_in, const int* in_sizes, int n_in,
                              void* d_out, int out_size)
{
  (void)in_sizes; (void)n_in; (void)out_size;
  const float* L     = (const float*)d_in[0];
  const float* A     = (const float*)d_in[1];
  const float* V     = (const float*)d_in[2];
  const float* attw  = (const float*)d_in[3];
  const float* attb  = (const float*)d_in[4];
  const float* gfw1  = (const float*)d_in[5];
  const float* gfb1  = (const float*)d_in[6];
  const float* gfw2  = (const float*)d_in[7];
  const float* gfb2  = (const float*)d_in[8];
  const float* gf2w1 = (const float*)d_in[9];
  const float* gf2b1 = (const float*)d_in[10];
  const float* gf2w2 = (const float*)d_in[11];
  const float* gf2b2 = (const float*)d_in[12];
  const float* llw1  = (const float*)d_in[13];
  const float* llb1  = (const float*)d_in[14];
  const float* llw2  = (const float*)d_in[15];
  const float* llb2  = (const float*)d_in[16];
  const float* llw3  = (const float*)d_in[17];
  const float* llb3  = (const float*)d_in[18];
  float* out = (float*)d_out;

  cudaFuncSetAttribute(k2_tc, cudaFuncAttributeMaxDynamicSharedMemorySize, SMEM_MLP_REQ);
  cudaFuncSetAttribute(k4_tc, cudaFuncAttributeMaxDynamicSharedMemorySize, SMEM_MLP_REQ);
  cudaFuncSetAttribute(k6_tc, cudaFuncAttributeMaxDynamicSharedMemorySize, SMEM_K6_REQ);

  k0_conv<<<dim3(36,3), 256>>>(gfw1, gfw2, gf2w1, gf2w2, llw1, llw2, llw3);
  k1_pre<<<NB/8, 256>>>(L, A, V, attw, attb);
  k2_tc<<<dim3(512,3), 256, SMEM_MLP_REQ>>>(gfb1, gfb2);
  k3_mid<<<NB/8, 256>>>();
  k4_tc<<<dim3(512,6), 256, SMEM_MLP_REQ>>>(gf2b1, gf2b2);
  k6_tc<<<512, 256, SMEM_K6_REQ>>>(llb1, llb2, llb3, out);
}

// round 17
// speedup vs baseline: 1.4110x; 1.0342x over previous
#include <cuda_runtime.h>
#include <cuda_fp16.h>
#include <cstdint>

// R17: grid transpose on k2/k4 — pair index moves to blockIdx.x so the 3/6
// CTAs sharing a row-tile run adjacently and share input rows through L2
// (previously tile-major order evicted them between uses; ~300MB DRAM saved).

#define NB 65536
#define DD 128
#define SLOT (NB*DD)
#define PSLOT (NB*64)

// ---------------- scratch ----------------
__device__ uint2 g_sPa[PSLOT];
__device__ uint2 g_sPv[PSLOT];
__device__ uint2 g_sPl[PSLOT];
__device__ uint2 g_sUni[PSLOT];
__device__ uint2 g_sBi[PSLOT];
__device__ uint2 g_sAV[PSLOT];
__device__ uint2 g_sAL[PSLOT];
__device__ uint2 g_sVL[PSLOT];
__device__ float g_G[3*SLOT];    // gav/gal/gvl fp32 (k2 -> k3)
__device__ float g_G2[6*SLOT];   // gf2 outputs fp32 (k4 -> k6)
__device__ float g_s[NB*16];

// packed 8B single-fp16 B-fragments: {b0, b1} per (k-step, n-tile, lane)
__device__ __align__(16) uint2 g_gfW1p[2][4096];
__device__ __align__(16) uint2 g_gfW2p[2][2048];
__device__ __align__(16) uint2 g_llW1p[6144];
__device__ __align__(16) uint2 g_llW2p[1024];
__device__ __align__(16) uint2 g_llW3p[2048];

extern __shared__ char smem_raw[];

// ---------------- helpers ----------------
__device__ __forceinline__ float wsum(float x){
  #pragma unroll
  for (int o=16;o;o>>=1) x += __shfl_xor_sync(0xffffffffu, x, o);
  return x;
}
__device__ __forceinline__ float wmax(float x){
  #pragma unroll
  for (int o=16;o;o>>=1) x = fmaxf(x, __shfl_xor_sync(0xffffffffu, x, o));
  return x;
}
__device__ __forceinline__ float dot4(float4 a, float4 b){
  return a.x*b.x + a.y*b.y + a.z*b.z + a.w*b.w;
}
__device__ __forceinline__ float max4(float4 a){ return fmaxf(fmaxf(a.x,a.y),fmaxf(a.z,a.w)); }
__device__ __forceinline__ float sum4(float4 a){ return a.x+a.y+a.z+a.w; }

__device__ __forceinline__ float fast_exp(float x){
  float e; asm("ex2.approx.f32 %0, %1;" : "=f"(e) : "f"(x*1.4426950408889634f));
  return e;
}
__device__ __forceinline__ float fast_tanh(float x){
  float e; asm("ex2.approx.f32 %0, %1;" : "=f"(e) : "f"(x*2.8853900817779268f));
  float r; asm("rcp.approx.f32 %0, %1;" : "=f"(r) : "f"(e+1.0f));
  return fmaf(-2.0f, r, 1.0f);
}

__device__ __forceinline__ uint32_t pack_h2(float x, float y){
  __half hx = __float2half_rn(x), hy = __float2half_rn(y);
  return (uint32_t)__half_as_ushort(hx) | ((uint32_t)__half_as_ushort(hy) << 16);
}
// fp16 split: hi = fp16(x), lo = fp16(x - hi)
__device__ __forceinline__ void split_pack2(float x, float y, uint32_t &h, uint32_t &l){
  __half hx = __float2half_rn(x), hy = __float2half_rn(y);
  float rx = x - __half2float(hx);
  float ry = y - __half2float(hy);
  h = (uint32_t)__half_as_ushort(hx) | ((uint32_t)__half_as_ushort(hy) << 16);
  l = pack_h2(rx, ry);
}
__device__ __forceinline__ uint2 split_u2(float x, float y){
  uint32_t h, l; split_pack2(x, y, h, l); return make_uint2(h, l);
}
__device__ __forceinline__ float2 unsplit(uint2 u){
  float2 a = __half22float2(*reinterpret_cast<__half2*>(&u.x));
  float2 b = __half22float2(*reinterpret_cast<__half2*>(&u.y));
  return make_float2(a.x + b.x, a.y + b.y);
}
__device__ __forceinline__ uint2 make_frag(float e0, float e1, float e2, float e3){
  return make_uint2(pack_h2(e0, e1), pack_h2(e2, e3));
}

#define MMA(c, a, bb0, bb1) \
  asm volatile("mma.sync.aligned.m16n8k16.row.col.f32.f16.f16.f32 " \
    "{%0,%1,%2,%3}, {%4,%5,%6,%7}, {%8,%9}, {%0,%1,%2,%3};" \
    : "+f"((c)[0]),"+f"((c)[1]),"+f"((c)[2]),"+f"((c)[3]) \
    : "r"((a)[0]),"r"((a)[1]),"r"((a)[2]),"r"((a)[3]), "r"(bb0),"r"(bb1))

__device__ __forceinline__ float lrelu(float x){ return (x > 0.f) ? x : 0.2f*x; }

// ---------------- K0: weight -> packed single-fp16 fragments ----------------
__global__ __launch_bounds__(256) void k0_conv(
    const float* __restrict__ gw1,  const float* __restrict__ gw2,
    const float* __restrict__ g2w1, const float* __restrict__ g2w2,
    const float* __restrict__ lw1,  const float* __restrict__ lw2,
    const float* __restrict__ lw3)
{
  int y = blockIdx.y;
  int e = blockIdx.x*256 + threadIdx.x;
  if (y < 2){
    if (e < 4096){
      int kk = e>>8, rem = e&255, nt = rem>>5, lane = rem&31, g = lane>>2, tg = lane&3;
      int n = nt*8+g, k = kk*16+tg*2;
      const float* w1 = y ? g2w1 : gw1;   // [256,64]
      g_gfW1p[y][e] = make_frag(w1[k*64+n], w1[(k+1)*64+n], w1[(k+8)*64+n], w1[(k+9)*64+n]);
    } else if (e < 6144){
      int f = e-4096;
      int q = f>>8, rem = f&255, nt = rem>>5, lane = rem&31, g = lane>>2, tg = lane&3;
      int nh = q>>2, kt = q&3;
      int n = (nh*8+nt)*8+g, k = kt*16+tg*2;
      const float* w2 = y ? g2w2 : gw2;   // [64,128]
      g_gfW2p[y][f] = make_frag(w2[k*128+n], w2[(k+1)*128+n], w2[(k+8)*128+n], w2[(k+9)*128+n]);
    }
  } else {
    if (e < 6144){
      int kk = e>>8, rem = e&255, nt = rem>>5, lane = rem&31, g = lane>>2, tg = lane&3;
      int n = nt*8+g, k = kk*16+tg*2;     // lw1 [384,64]
      g_llW1p[e] = make_frag(lw1[k*64+n], lw1[(k+1)*64+n], lw1[(k+8)*64+n], lw1[(k+9)*64+n]);
    } else if (e < 7168){
      int f = e-6144;
      int kt = f>>8, rem = f&255, nt = rem>>5, lane = rem&31, g = lane>>2, tg = lane&3;
      int n = nt*8+g, k = kt*16+tg*2;     // lw2 [64,64]
      g_llW2p[f] = make_frag(lw2[k*64+n], lw2[(k+1)*64+n], lw2[(k+8)*64+n], lw2[(k+9)*64+n]);
    } else if (e < 9216){
      int f = e-7168;
      int q = f>>8, rem = f&255, nt = rem>>5, lane = rem&31, g = lane>>2, tg = lane&3;
      int nh = q>>2, kt = q&3;
      int n = (nh*8+nt)*8+g, k = kt*16+tg*2;  // lw3 [64,128]
      g_llW3p[f] = make_frag(lw3[k*128+n], lw3[(k+1)*128+n], lw3[(k+8)*128+n], lw3[(k+9)*128+n]);
    }
  }
}

// ---------------- K1: rowwise pre ----------------
__global__ __launch_bounds__(256) void k1_pre(
    const float* __restrict__ L, const float* __restrict__ A,
    const float* __restrict__ V, const float* __restrict__ attw,
    const float* __restrict__ attb)
{
  int gw   = (int)((blockIdx.x*blockDim.x + threadIdx.x) >> 5);
  int lane = threadIdx.x & 31;
  size_t base = (size_t)gw*DD + lane*4;
  size_t pbase = (size_t)gw*64 + lane*2;

  float4 av = *(const float4*)(A+base);
  float4 vv = *(const float4*)(V+base);
  float4 lv = *(const float4*)(L+base);
  float4 wv = *(const float4*)(attw + lane*4);
  float bb = attb[0];

  float sa = fast_tanh(wsum(dot4(av,wv)) + bb);
  float sv = fast_tanh(wsum(dot4(vv,wv)) + bb);
  float sl = fast_tanh(wsum(dot4(lv,wv)) + bb);

  float4 u;
  u.x = (sa*av.x + sv*vv.x + sl*lv.x)*(1.0f/3.0f);
  u.y = (sa*av.y + sv*vv.y + sl*lv.y)*(1.0f/3.0f);
  u.z = (sa*av.z + sv*vv.z + sl*lv.z)*(1.0f/3.0f);
  u.w = (sa*av.w + sv*vv.w + sl*lv.w)*(1.0f/3.0f);
  g_sUni[pbase]   = split_u2(u.x, u.y);
  g_sUni[pbase+1] = split_u2(u.z, u.w);

  float m = wmax(max4(av));
  float4 pa = make_float4(fast_exp(av.x-m),fast_exp(av.y-m),fast_exp(av.z-m),fast_exp(av.w-m));
  float inv = 1.0f/wsum(sum4(pa));
  pa.x*=inv; pa.y*=inv; pa.z*=inv; pa.w*=inv;
  m = wmax(max4(vv));
  float4 pv = make_float4(fast_exp(vv.x-m),fast_exp(vv.y-m),fast_exp(vv.z-m),fast_exp(vv.w-m));
  inv = 1.0f/wsum(sum4(pv));
  pv.x*=inv; pv.y*=inv; pv.z*=inv; pv.w*=inv;
  m = wmax(max4(lv));
  float4 pl = make_float4(fast_exp(lv.x-m),fast_exp(lv.y-m),fast_exp(lv.z-m),fast_exp(lv.w-m));
  inv = 1.0f/wsum(sum4(pl));
  pl.x*=inv; pl.y*=inv; pl.z*=inv; pl.w*=inv;

  g_sPa[pbase]   = split_u2(pa.x, pa.y);
  g_sPa[pbase+1] = split_u2(pa.z, pa.w);
  g_sPv[pbase]   = split_u2(pv.x, pv.y);
  g_sPv[pbase+1] = split_u2(pv.z, pv.w);
  g_sPl[pbase]   = split_u2(pl.x, pl.y);
  g_sPl[pbase+1] = split_u2(pl.z, pl.w);

  float dav = wsum(dot4(pa,pv));
  float dal = wsum(dot4(pa,pl));
  float dvl = wsum(dot4(pv,pl));

  float sav = (sa+sv)/(dav+0.5f);
  float sal = (sa+sl)/(dal+0.5f);
  float svl = (sl+sv)/(dvl+0.5f);

  float m3 = fmaxf(sav,fmaxf(sal,svl));
  float e0 = fast_exp(sav-m3), e1 = fast_exp(sal-m3), e2 = fast_exp(svl-m3);
  float r3 = 1.0f/(e0+e1+e2);

  if (lane==0){
    float* s = g_s + (size_t)gw*16;
    s[0]=sa; s[1]=sv; s[2]=sl;
    s[3]=sav; s[4]=sal; s[5]=svl;
    s[6]=e0*r3; s[7]=e1*r3; s[8]=e2*r3;
  }
}

// ---------------- 2-layer MLP body (packed fp16 weights in smem, occ 2) ----------------
// smem: 0 b1s(256B) | 256 b2s(512B) | 1024 W1p(32768) | 33792 W2p(16384) = 50176
#define SMEM_MLP_REQ 50176

__device__ __forceinline__ void mlp2_body(
    const uint2* __restrict__ x1, const uint2* __restrict__ x2,
    float* __restrict__ outp, int row0, int n2slot)
{
  const float* b1s = (const float*)(smem_raw);
  const float* b2s = (const float*)(smem_raw + 256);
  const uint2* W1p = (const uint2*)(smem_raw + 1024);
  const uint2* W2p = (const uint2*)(smem_raw + 33792);

  int tid = threadIdx.x;
  int w = tid >> 5, lane = tid & 31;
  int g = lane >> 2, tg = lane & 3;
  int r0 = row0 + w*16 + g;
  int r1 = r0 + 8;

  // -------- stage 1: concat(x1,x2)[128x256] @ W1 --------
  float acc[8][4];
  #pragma unroll
  for (int i=0;i<8;i++){ acc[i][0]=0.f; acc[i][1]=0.f; acc[i][2]=0.f; acc[i][3]=0.f; }

  uint2 cu0, cu1, cu2, cu3;
  {
    const uint2* p0 = x1 + (size_t)r0*64 + tg;
    const uint2* p1 = x1 + (size_t)r1*64 + tg;
    cu0 = p0[0]; cu1 = p1[0]; cu2 = p0[4]; cu3 = p1[4];
  }
  #pragma unroll 1
  for (int kk = 0; kk < 16; kk++){
    uint32_t ah[4], al[4];
    ah[0]=cu0.x; al[0]=cu0.y;
    ah[1]=cu1.x; al[1]=cu1.y;
    ah[2]=cu2.x; al[2]=cu2.y;
    ah[3]=cu3.x; al[3]=cu3.y;
    if (kk < 15){
      int k2i = kk + 1;
      const uint2* s2 = (k2i < 8) ? x1 : x2;
      int pi2 = (k2i & 7)*8 + tg;
      const uint2* p0 = s2 + (size_t)r0*64 + pi2;
      const uint2* p1 = s2 + (size_t)r1*64 + pi2;
      cu0 = p0[0]; cu1 = p1[0]; cu2 = p0[4]; cu3 = p1[4];
    }
    const uint2* bp = W1p + kk*256 + lane;
    #pragma unroll
    for (int nt = 0; nt < 8; nt++){
      uint2 B = bp[nt*32];
      MMA(acc[nt], ah, B.x, B.y);
      MMA(acc[nt], al, B.x, B.y);
    }
  }

  // -------- H = lrelu(acc + b1) -> frags --------
  uint32_t hh[4][4], hl[4][4];
  #pragma unroll
  for (int kt = 0; kt < 4; kt++){
    float* t0 = acc[2*kt];
    float* t1 = acc[2*kt+1];
    int c0 = kt*16 + tg*2;
    float bA = b1s[c0], bB = b1s[c0+1], bC = b1s[c0+8], bD = b1s[c0+9];
    split_pack2(lrelu(t0[0]+bA), lrelu(t0[1]+bB), hh[kt][0], hl[kt][0]);
    split_pack2(lrelu(t0[2]+bA), lrelu(t0[3]+bB), hh[kt][1], hl[kt][1]);
    split_pack2(lrelu(t1[0]+bC), lrelu(t1[1]+bD), hh[kt][2], hl[kt][2]);
    split_pack2(lrelu(t1[2]+bC), lrelu(t1[3]+bD), hh[kt][3], hl[kt][3]);
  }

  // -------- stage 2: H[128x64] @ W2[64x128] --------
  float scv0 = 0.f, scv1 = 0.f;
  if (n2slot >= 0){
    scv0 = g_s[(size_t)r0*16 + n2slot];
    scv1 = g_s[(size_t)r1*16 + n2slot];
  }
  #pragma unroll 1
  for (int nh = 0; nh < 2; nh++){
    float acc2[8][4];
    #pragma unroll
    for (int i=0;i<8;i++){ acc2[i][0]=0.f; acc2[i][1]=0.f; acc2[i][2]=0.f; acc2[i][3]=0.f; }
    const uint2* bp2 = W2p + nh*1024 + lane;
    #pragma unroll
    for (int nt = 0; nt < 8; nt++){
      #pragma unroll
      for (int kt = 0; kt < 4; kt++){
        uint2 B = bp2[kt*256 + nt*32];
        MMA(acc2[nt], hh[kt], B.x, B.y);
        MMA(acc2[nt], hl[kt], B.x, B.y);
      }
    }
    #pragma unroll
    for (int nt = 0; nt < 8; nt++){
      int col = (nh*8+nt)*8 + tg*2;
      float v0 = fast_tanh(acc2[nt][0] + b2s[col]);
      float v1 = fast_tanh(acc2[nt][1] + b2s[col+1]);
      float v2 = fast_tanh(acc2[nt][2] + b2s[col]);
      float v3 = fast_tanh(acc2[nt][3] + b2s[col+1]);
      if (n2slot >= 0){
        v0 = fast_tanh(scv0*v0); v1 = fast_tanh(scv0*v1);
        v2 = fast_tanh(scv1*v2); v3 = fast_tanh(scv1*v3);
      }
      *(float2*)(outp + (size_t)r0*DD + col) = make_float2(v0, v1);
      *(float2*)(outp + (size_t)r1*DD + col) = make_float2(v2, v3);
    }
  }
}

__device__ __forceinline__ void stage_mlp_weights(int set,
    const float* __restrict__ b1, const float* __restrict__ b2)
{
  float* b1s = (float*)(smem_raw);
  float* b2s = (float*)(smem_raw + 256);
  uint4* dW1 = (uint4*)(smem_raw + 1024);
  uint4* dW2 = (uint4*)(smem_raw + 33792);
  int tid = threadIdx.x;
  const uint4* s1 = (const uint4*)g_gfW1p[set];
  const uint4* s2 = (const uint4*)g_gfW2p[set];
  #pragma unroll
  for (int i = tid; i < 2048; i += 256) dW1[i] = s1[i];
  #pragma unroll
  for (int i = tid; i < 1024; i += 256) dW2[i] = s2[i];
  if (tid < 64)  b1s[tid] = b1[tid];
  if (tid < 128) b2s[tid] = b2[tid];
  __syncthreads();
}

// ---------------- K2 / K4 (occ 2, pair-major grid for L2 reuse) ----------------
__global__ __launch_bounds__(256,2) void k2_tc(const float* __restrict__ b1, const float* __restrict__ b2)
{
  stage_mlp_weights(0, b1, b2);
  const uint2 *x1, *x2;
  int p = blockIdx.x;            // pair index (fast dim -> same tile adjacent)
  int t = blockIdx.y;            // tile index
  if (p==0){ x1=g_sPa; x2=g_sPv; }
  else if (p==1){ x1=g_sPa; x2=g_sPl; }
  else { x1=g_sPv; x2=g_sPl; }
  mlp2_body(x1, x2, g_G + (size_t)p*SLOT, t*128, -1);
}

__global__ __launch_bounds__(256,2) void k4_tc(const float* __restrict__ b1, const float* __restrict__ b2)
{
  stage_mlp_weights(1, b1, b2);
  const uint2 *x1, *x2;
  int p = blockIdx.x;            // pair index (fast dim -> same tile adjacent)
  int t = blockIdx.y;            // tile index
  switch(p){
    case 0: x1=g_sAV; x2=g_sVL; break;
    case 1: x1=g_sAV; x2=g_sAL; break;
    case 2: x1=g_sVL; x2=g_sAL; break;
    case 3: x1=g_sAV; x2=g_sPl; break;
    case 4: x1=g_sAL; x2=g_sPv; break;
    default:x1=g_sVL; x2=g_sPa; break;
  }
  mlp2_body(x1, x2, g_G2 + (size_t)p*SLOT, t*128, 9+p);
}

// ---------------- K3: rowwise mid ----------------
__global__ __launch_bounds__(256) void k3_mid()
{
  int gw   = (int)((blockIdx.x*blockDim.x + threadIdx.x) >> 5);
  int lane = threadIdx.x & 31;
  size_t base = (size_t)gw*DD + lane*4;
  size_t pbase = (size_t)gw*64 + lane*2;

  float4 gav = *(const float4*)(g_G + base);
  float4 gal = *(const float4*)(g_G + (size_t)SLOT + base);
  float4 gvl = *(const float4*)(g_G + 2*(size_t)SLOT + base);

  float2 t0, t1;
  t0 = unsplit(g_sPa[pbase]); t1 = unsplit(g_sPa[pbase+1]);
  float4 pa = make_float4(t0.x, t0.y, t1.x, t1.y);
  t0 = unsplit(g_sPv[pbase]); t1 = unsplit(g_sPv[pbase+1]);
  float4 pv = make_float4(t0.x, t0.y, t1.x, t1.y);
  t0 = unsplit(g_sPl[pbase]); t1 = unsplit(g_sPl[pbase+1]);
  float4 pl = make_float4(t0.x, t0.y, t1.x, t1.y);

  float m, inv;
  m = wmax(max4(gav));
  float4 A2 = make_float4(fast_exp(gav.x-m),fast_exp(gav.y-m),fast_exp(gav.z-m),fast_exp(gav.w-m));
  inv = 1.0f/wsum(sum4(A2)); A2.x*=inv; A2.y*=inv; A2.z*=inv; A2.w*=inv;
  m = wmax(max4(gal));
  float4 L2 = make_float4(fast_exp(gal.x-m),fast_exp(gal.y-m),fast_exp(gal.z-m),fast_exp(gal.w-m));
  inv = 1.0f/wsum(sum4(L2)); L2.x*=inv; L2.y*=inv; L2.z*=inv; L2.w*=inv;
  m = wmax(max4(gvl));
  float4 V2 = make_float4(fast_exp(gvl.x-m),fast_exp(gvl.y-m),fast_exp(gvl.z-m),fast_exp(gvl.w-m));
  inv = 1.0f/wsum(sum4(V2)); V2.x*=inv; V2.y*=inv; V2.z*=inv; V2.w*=inv;

  float d0 = wsum(dot4(A2,V2));
  float d1 = wsum(dot4(A2,L2));
  float d2 = wsum(dot4(L2,V2));
  float d3 = wsum(dot4(A2,pl));
  float d4 = wsum(dot4(L2,pv));
  float d5 = wsum(dot4(V2,pa));

  const float* s = g_s + (size_t)gw*16;
  float sa1=s[0], sv1=s[1], sl1=s[2], sav=s[3], sal=s[4], svl=s[5];
  float nm0=s[6], nm1=s[7], nm2=s[8];

  float e0=(sav+svl)/(d0+0.5f);
  float e1=(sav+sal)/(d1+0.5f);
  float e2=(sal+svl)/(d2+0.5f);
  float e3=(sav+sl1)/(d3+0.5f);
  float e4=(sal+sv1)/(d4+0.5f);
  float e5=(sa1+svl)/(d5+0.5f);
  float mm = fmaxf(fmaxf(fmaxf(e0,e1),fmaxf(e2,e3)),fmaxf(e4,e5));
  float x0=fast_exp(e0-mm),x1=fast_exp(e1-mm),x2=fast_exp(e2-mm);
  float x3=fast_exp(e3-mm),x4=fast_exp(e4-mm),x5=fast_exp(e5-mm);
  float ri = 1.0f/(x0+x1+x2+x3+x4+x5);
  if (lane==0){
    float* sw = g_s + (size_t)gw*16;
    sw[9]=x0*ri; sw[10]=x1*ri; sw[11]=x2*ri; sw[12]=x3*ri; sw[13]=x4*ri; sw[14]=x5*ri;
  }

  float4 AV = make_float4(fast_tanh(nm0*gav.x),fast_tanh(nm0*gav.y),fast_tanh(nm0*gav.z),fast_tanh(nm0*gav.w));
  float4 AL = make_float4(fast_tanh(nm1*gal.x),fast_tanh(nm1*gal.y),fast_tanh(nm1*gal.z),fast_tanh(nm1*gal.w));
  float4 VL = make_float4(fast_tanh(nm2*gvl.x),fast_tanh(nm2*gvl.y),fast_tanh(nm2*gvl.z),fast_tanh(nm2*gvl.w));

  g_sAV[pbase]   = split_u2(AV.x, AV.y);
  g_sAV[pbase+1] = split_u2(AV.z, AV.w);
  g_sAL[pbase]   = split_u2(AL.x, AL.y);
  g_sAL[pbase+1] = split_u2(AL.z, AL.w);
  g_sVL[pbase]   = split_u2(VL.x, VL.y);
  g_sVL[pbase+1] = split_u2(VL.z, VL.w);

  float4 bi = make_float4(AV.x+AL.x+VL.x, AV.y+AL.y+VL.y, AV.z+AL.z+VL.z, AV.w+AL.w+VL.w);
  g_sBi[pbase]   = split_u2(bi.x, bi.y);
  g_sBi[pbase+1] = split_u2(bi.z, bi.w);
}

// ---------------- K6: fused 3-layer head (tri summed inline, occ 2) ----------------
// smem: 0 b1s | 256 b2s | 512 b3s | 1024 W1p(49152) | 50176 W2p(8192) | 58368 W3p(16384) = 74752
#define SMEM_K6_REQ 74752

__global__ __launch_bounds__(256,2) void k6_tc(
    const float* __restrict__ b1, const float* __restrict__ b2,
    const float* __restrict__ b3, float* __restrict__ out)
{
  float* b1s = (float*)(smem_raw);
  float* b2s = (float*)(smem_raw + 256);
  float* b3s = (float*)(smem_raw + 512);
  uint2* W1p = (uint2*)(smem_raw + 1024);
  uint2* W2p = (uint2*)(smem_raw + 50176);
  uint2* W3p = (uint2*)(smem_raw + 58368);

  int tid = threadIdx.x;
  int row0 = blockIdx.x * 128;

  {
    uint4* d1 = (uint4*)W1p; const uint4* s1 = (const uint4*)g_llW1p;
    #pragma unroll
    for (int i = tid; i < 3072; i += 256) d1[i] = s1[i];
    uint4* d2 = (uint4*)W2p; const uint4* s2 = (const uint4*)g_llW2p;
    #pragma unroll
    for (int i = tid; i < 512; i += 256) d2[i] = s2[i];
    uint4* d3 = (uint4*)W3p; const uint4* s3 = (const uint4*)g_llW3p;
    #pragma unroll
    for (int i = tid; i < 1024; i += 256) d3[i] = s3[i];
  }
  if (tid < 64)  b1s[tid] = b1[tid];
  if (tid < 64)  b2s[tid] = b2[tid];
  if (tid < 128) b3s[tid] = b3[tid];
  __syncthreads();

  int w = tid >> 5, lane = tid & 31;
  int g = lane >> 2, tg = lane & 3;
  int r0 = row0 + w*16 + g;
  int r1 = r0 + 8;

  // -------- layer 1: fusion[128x384] @ W1[384x64] --------
  float acc[8][4];
  #pragma unroll
  for (int i=0;i<8;i++){ acc[i][0]=0.f; acc[i][1]=0.f; acc[i][2]=0.f; acc[i][3]=0.f; }

  #pragma unroll 1
  for (int kk = 0; kk < 24; kk++){
    int ch = kk >> 3;
    uint32_t ah[4], al[4];
    if (ch < 2){
      const uint2* sp = (ch == 0) ? g_sUni : g_sBi;
      int pi = (kk & 7)*8 + tg;
      const uint2* p0 = sp + (size_t)r0*64 + pi;
      const uint2* p1 = sp + (size_t)r1*64 + pi;
      uint2 u00 = p0[0], u01 = p0[4];
      uint2 u10 = p1[0], u11 = p1[4];
      ah[0]=u00.x; al[0]=u00.y;
      ah[1]=u10.x; al[1]=u10.y;
      ah[2]=u01.x; al[2]=u01.y;
      ah[3]=u11.x; al[3]=u11.y;
    } else {
      int cc = (kk & 7)*16 + tg*2;
      size_t o0 = (size_t)r0*DD + cc;
      size_t o1 = (size_t)r1*DD + cc;
      float2 v00 = *(const float2*)(g_G2 + o0);
      float2 v01 = *(const float2*)(g_G2 + o0 + 8);
      float2 v10 = *(const float2*)(g_G2 + o1);
      float2 v11 = *(const float2*)(g_G2 + o1 + 8);
      #pragma unroll
      for (int p = 1; p < 6; p++){
        size_t po = (size_t)p*SLOT;
        float2 q;
        q = *(const float2*)(g_G2 + po + o0);     v00.x+=q.x; v00.y+=q.y;
        q = *(const float2*)(g_G2 + po + o0 + 8); v01.x+=q.x; v01.y+=q.y;
        q = *(const float2*)(g_G2 + po + o1);     v10.x+=q.x; v10.y+=q.y;
        q = *(const float2*)(g_G2 + po + o1 + 8); v11.x+=q.x; v11.y+=q.y;
      }
      split_pack2(v00.x, v00.y, ah[0], al[0]);
      split_pack2(v10.x, v10.y, ah[1], al[1]);
      split_pack2(v01.x, v01.y, ah[2], al[2]);
      split_pack2(v11.x, v11.y, ah[3], al[3]);
    }
    const uint2* bp = W1p + kk*256 + lane;
    #pragma unroll
    for (int nt = 0; nt < 8; nt++){
      uint2 B = bp[nt*32];
      MMA(acc[nt], ah, B.x, B.y);
      MMA(acc[nt], al, B.x, B.y);
    }
  }

  uint32_t hh[4][4], hl[4][4];
  #pragma unroll
  for (int kt = 0; kt < 4; kt++){
    float* q0 = acc[2*kt];
    float* q1 = acc[2*kt+1];
    int c0 = kt*16 + tg*2;
    float bA = b1s[c0], bB = b1s[c0+1], bC = b1s[c0+8], bD = b1s[c0+9];
    split_pack2(fast_tanh(q0[0]+bA), fast_tanh(q0[1]+bB), hh[kt][0], hl[kt][0]);
    split_pack2(fast_tanh(q0[2]+bA), fast_tanh(q0[3]+bB), hh[kt][1], hl[kt][1]);
    split_pack2(fast_tanh(q1[0]+bC), fast_tanh(q1[1]+bD), hh[kt][2], hl[kt][2]);
    split_pack2(fast_tanh(q1[2]+bC), fast_tanh(q1[3]+bD), hh[kt][3], hl[kt][3]);
  }

  // -------- layer 2: H1[128x64] @ W2[64x64] --------
  #pragma unroll
  for (int i=0;i<8;i++){ acc[i][0]=0.f; acc[i][1]=0.f; acc[i][2]=0.f; acc[i][3]=0.f; }
  #pragma unroll
  for (int nt = 0; nt < 8; nt++){
    #pragma unroll
    for (int kt = 0; kt < 4; kt++){
      uint2 B = W2p[kt*256 + nt*32 + lane];
      MMA(acc[nt], hh[kt], B.x, B.y);
      MMA(acc[nt], hl[kt], B.x, B.y);
    }
  }
  #pragma unroll
  for (int kt = 0; kt < 4; kt++){
    float* q0 = acc[2*kt];
    float* q1 = acc[2*kt+1];
    int c0 = kt*16 + tg*2;
    float bA = b2s[c0], bB = b2s[c0+1], bC = b2s[c0+8], bD = b2s[c0+9];
    split_pack2(fast_tanh(q0[0]+bA), fast_tanh(q0[1]+bB), hh[kt][0], hl[kt][0]);
    split_pack2(fast_tanh(q0[2]+bA), fast_tanh(q0[3]+bB), hh[kt][1], hl[kt][1]);
    split_pack2(fast_tanh(q1[0]+bC), fast_tanh(q1[1]+bD), hh[kt][2], hl[kt][2]);
    split_pack2(fast_tanh(q1[2]+bC), fast_tanh(q1[3]+bD), hh[kt][3], hl[kt][3]);
  }

  // -------- layer 3: H2[128x64] @ W3[64x128] --------
  #pragma unroll 1
  for (int nh = 0; nh < 2; nh++){
    float acc2[8][4];
    #pragma unroll
    for (int i=0;i<8;i++){ acc2[i][0]=0.f; acc2[i][1]=0.f; acc2[i][2]=0.f; acc2[i][3]=0.f; }
    const uint2* bp3 = W3p + nh*1024 + lane;
    #pragma unroll
    for (int nt = 0; nt < 8; nt++){
      #pragma unroll
      for (int kt = 0; kt < 4; kt++){
        uint2 B = bp3[kt*256 + nt*32];
        MMA(acc2[nt], hh[kt], B.x, B.y);
        MMA(acc2[nt], hl[kt], B.x, B.y);
      }
    }
    #pragma unroll
    for (int nt = 0; nt < 8; nt++){
      int col = (nh*8+nt)*8 + tg*2;
      float v0 = fast_tanh(acc2[nt][0] + b3s[col]);
      float v1 = fast_tanh(acc2[nt][1] + b3s[col+1]);
      float v2 = fast_tanh(acc2[nt][2] + b3s[col]);
      float v3 = fast_tanh(acc2[nt][3] + b3s[col+1]);
      *(float2*)(out + (size_t)r0*DD + col) = make_float2(v0, v1);
      *(float2*)(out + (size_t)r1*DD + col) = make_float2(v2, v3);
    }
  }
}

// ---------------- launch ----------------
extern "C" void kernel_launch(void* const* d_in, const int* in_sizes, int n_in,
                              void* d_out, int out_size)
{
  (void)in_sizes; (void)n_in; (void)out_size;
  const float* L     = (const float*)d_in[0];
  const float* A     = (const float*)d_in[1];
  const float* V     = (const float*)d_in[2];
  const float* attw  = (const float*)d_in[3];
  const float* attb  = (const float*)d_in[4];
  const float* gfw1  = (const float*)d_in[5];
  const float* gfb1  = (const float*)d_in[6];
  const float* gfw2  = (const float*)d_in[7];
  const float* gfb2  = (const float*)d_in[8];
  const float* gf2w1 = (const float*)d_in[9];
  const float* gf2b1 = (const float*)d_in[10];
  const float* gf2w2 = (const float*)d_in[11];
  const float* gf2b2 = (const float*)d_in[12];
  const float* llw1  = (const float*)d_in[13];
  const float* llb1  = (const float*)d_in[14];
  const float* llw2  = (const float*)d_in[15];
  const float* llb2  = (const float*)d_in[16];
  const float* llw3  = (const float*)d_in[17];
  const float* llb3  = (const float*)d_in[18];
  float* out = (float*)d_out;

  cudaFuncSetAttribute(k2_tc, cudaFuncAttributeMaxDynamicSharedMemorySize, SMEM_MLP_REQ);
  cudaFuncSetAttribute(k4_tc, cudaFuncAttributeMaxDynamicSharedMemorySize, SMEM_MLP_REQ);
  cudaFuncSetAttribute(k6_tc, cudaFuncAttributeMaxDynamicSharedMemorySize, SMEM_K6_REQ);

  k0_conv<<<dim3(36,3), 256>>>(gfw1, gfw2, gf2w1, gf2w2, llw1, llw2, llw3);
  k1_pre<<<NB/8, 256>>>(L, A, V, attw, attb);
  k2_tc<<<dim3(3,512), 256, SMEM_MLP_REQ>>>(gfb1, gfb2);
  k3_mid<<<NB/8, 256>>>();
  k4_tc<<<dim3(6,512), 256, SMEM_MLP_REQ>>>(gf2b1, gf2b2);
  k6_tc<<<512, 256, SMEM_K6_REQ>>>(llb1, llb2, llb3, out);
}